// round 11
// baseline (speedup 1.0000x reference)
#include <cuda_runtime.h>
#include <cuda_bf16.h>
#include <cstdint>

// Problem constants
#define B_   4
#define N_   1024
#define D_   1024
#define H_   16
#define DH_  64
#define M_   (B_ * N_)    // 4096
#define BH_  (B_ * H_)    // 64

// Scratch (allocation-free rule: __device__ globals)
__device__ __nv_bfloat16 g_pjh[3][(size_t)M_ * D_];   // projected q,k,v hi
__device__ __nv_bfloat16 g_pjl[3][(size_t)M_ * D_];   // projected q,k,v lo
__device__ __nv_bfloat16 g_inh[3][(size_t)M_ * D_];
__device__ __nv_bfloat16 g_inl[3][(size_t)M_ * D_];
__device__ __nv_bfloat16 g_wth[4][(size_t)D_ * D_];
__device__ __nv_bfloat16 g_wtl[4][(size_t)D_ * D_];
__device__ __nv_bfloat16 g_ah[(size_t)M_ * D_];
__device__ __nv_bfloat16 g_al[(size_t)M_ * D_];
__device__ float g_rmax[(size_t)BH_ * N_];            // per-row final max
__device__ float g_rinv[(size_t)BH_ * N_];            // per-row 1/sum
__device__ int   g_mask4;

struct Bias3 { const float* p[3]; };
struct Src4  { const float* p[4]; };

// ===========================================================================
// Helpers (generic PTX, sm_80+ only)
// ===========================================================================
__device__ __forceinline__ uint32_t smem_u32(const void* p) {
    uint32_t a;
    asm("{ .reg .u64 t; cvta.to.shared.u64 t, %1; cvt.u32.u64 %0, t; }" : "=r"(a) : "l"(p));
    return a;
}
__device__ __forceinline__ void ldsm_x4(uint32_t* r, uint32_t addr) {
    asm volatile("ldmatrix.sync.aligned.m8n8.x4.shared.b16 {%0,%1,%2,%3}, [%4];"
                 : "=r"(r[0]), "=r"(r[1]), "=r"(r[2]), "=r"(r[3]) : "r"(addr));
}
__device__ __forceinline__ void ldsm_x4_t(uint32_t* r, uint32_t addr) {
    asm volatile("ldmatrix.sync.aligned.m8n8.x4.trans.shared.b16 {%0,%1,%2,%3}, [%4];"
                 : "=r"(r[0]), "=r"(r[1]), "=r"(r[2]), "=r"(r[3]) : "r"(addr));
}
__device__ __forceinline__ void mma_bf16(float* c, const uint32_t* a, const uint32_t* b) {
    asm volatile(
        "mma.sync.aligned.m16n8k16.row.col.f32.bf16.bf16.f32 "
        "{%0,%1,%2,%3}, {%4,%5,%6,%7}, {%8,%9}, {%0,%1,%2,%3};"
        : "+f"(c[0]), "+f"(c[1]), "+f"(c[2]), "+f"(c[3])
        : "r"(a[0]), "r"(a[1]), "r"(a[2]), "r"(a[3]), "r"(b[0]), "r"(b[1]));
}
__device__ __forceinline__ void cp16(uint32_t smem, const void* g) {
    asm volatile("cp.async.ca.shared.global [%0], [%1], 16;" :: "r"(smem), "l"(g));
}
__device__ __forceinline__ void cp_commit() { asm volatile("cp.async.commit_group;"); }
template <int N>
__device__ __forceinline__ void cp_wait() { asm volatile("cp.async.wait_group %0;" :: "n"(N)); }

// ===========================================================================
// fp32 -> bf16 hi/lo conversion
// ===========================================================================
__device__ __forceinline__ void cvt_body(const float* __restrict__ src,
                                         __nv_bfloat16* __restrict__ dh,
                                         __nv_bfloat16* __restrict__ dl, int i) {
    float4 v = ((const float4*)src)[i];
    __nv_bfloat16 h0 = __float2bfloat16(v.x), h1 = __float2bfloat16(v.y);
    __nv_bfloat16 h2 = __float2bfloat16(v.z), h3 = __float2bfloat16(v.w);
    __nv_bfloat16 l0 = __float2bfloat16(v.x - __bfloat162float(h0));
    __nv_bfloat16 l1 = __float2bfloat16(v.y - __bfloat162float(h1));
    __nv_bfloat16 l2 = __float2bfloat16(v.z - __bfloat162float(h2));
    __nv_bfloat16 l3 = __float2bfloat16(v.w - __bfloat162float(h3));
    ((__nv_bfloat162*)dh)[i * 2]     = __nv_bfloat162(h0, h1);
    ((__nv_bfloat162*)dh)[i * 2 + 1] = __nv_bfloat162(h2, h3);
    ((__nv_bfloat162*)dl)[i * 2]     = __nv_bfloat162(l0, l1);
    ((__nv_bfloat162*)dl)[i * 2 + 1] = __nv_bfloat162(l2, l3);
}
__global__ void cvt_hilo(const float* __restrict__ src,
                         __nv_bfloat16* __restrict__ dh,
                         __nv_bfloat16* __restrict__ dl, int n4) {
    const int i = blockIdx.x * blockDim.x + threadIdx.x;
    if (i < n4) cvt_body(src, dh, dl, i);
}
__global__ void cvt_hilo4(Src4 s4, __nv_bfloat16* __restrict__ dh,
                          __nv_bfloat16* __restrict__ dl, int n4) {
    const int i = blockIdx.x * blockDim.x + threadIdx.x;
    const int z = blockIdx.z;
    if (i < n4) cvt_body(s4.p[z], dh + (size_t)z * D_ * D_, dl + (size_t)z * D_ * D_, i);
}

// ===========================================================================
// bf16x3 NT GEMM (R6 2-stage version, z-batched).
// ===========================================================================
#define BK_      32
#define LDS_     40
#define TILE_B   (128 * LDS_ * 2)
#define BUF_B    (4 * TILE_B)
#define NUM_KB   (D_ / BK_)

template <int MODE>
__global__ void __launch_bounds__(256, 1) gemm_mma(const __nv_bfloat16* __restrict__ Ah,
                                                   const __nv_bfloat16* __restrict__ Al,
                                                   const __nv_bfloat16* __restrict__ Bh,
                                                   const __nv_bfloat16* __restrict__ Bl,
                                                   Bias3 b3,
                                                   float* __restrict__ C,
                                                   __nv_bfloat16* __restrict__ Chi,
                                                   __nv_bfloat16* __restrict__ Clo) {
    extern __shared__ char smem[];
    __shared__ float s_bias[128];

    const int z = blockIdx.z;
    Ah += (size_t)z * M_ * D_;
    Al += (size_t)z * M_ * D_;
    Bh += (size_t)z * D_ * D_;
    Bl += (size_t)z * D_ * D_;
    const float* bias = b3.p[z];
    if (MODE == 1) { Chi += (size_t)z * M_ * D_; Clo += (size_t)z * M_ * D_; }

    const int tid = threadIdx.x;
    const int wid = tid >> 5;
    const int lane = tid & 31;
    const int warp_m = wid >> 2;
    const int warp_n = wid & 3;
    const int row0 = blockIdx.y * 128;
    const int col0 = blockIdx.x * 128;

    if (tid < 128) s_bias[tid] = bias[col0 + tid];

    const int r  = tid >> 1;
    const int half = tid & 1;
    const __nv_bfloat16* Ah_p = Ah + (size_t)(row0 + r) * D_ + half * 16;
    const __nv_bfloat16* Al_p = Al + (size_t)(row0 + r) * D_ + half * 16;
    const __nv_bfloat16* Bh_p = Bh + (size_t)(col0 + r) * D_ + half * 16;
    const __nv_bfloat16* Bl_p = Bl + (size_t)(col0 + r) * D_ + half * 16;
    const uint32_t sb = smem_u32(smem);
    const uint32_t st = sb + (uint32_t)r * (LDS_ * 2) + (uint32_t)half * 32;

    const int seg = lane >> 3, l7 = lane & 7;
    const int a_row = warp_m * 64 + (seg & 1) * 8 + l7;
    const int a_colb = (((seg >> 1) & 1) * 8) * 2;
    const int b_row = warp_n * 32 + ((seg >> 1) & 1) * 8 + l7;
    const int b_colb = ((seg & 1) * 8) * 2;

    float acc[4][4][4] = {};

    {
        cp16(st + 0*TILE_B,      Ah_p);
        cp16(st + 0*TILE_B + 16, Ah_p + 8);
        cp16(st + 1*TILE_B,      Al_p);
        cp16(st + 1*TILE_B + 16, Al_p + 8);
        cp16(st + 2*TILE_B,      Bh_p);
        cp16(st + 2*TILE_B + 16, Bh_p + 8);
        cp16(st + 3*TILE_B,      Bl_p);
        cp16(st + 3*TILE_B + 16, Bl_p + 8);
        cp_commit();
    }

    for (int kb = 0; kb < NUM_KB; kb++) {
        if (kb + 1 < NUM_KB) {
            const int k0 = (kb + 1) * BK_;
            const uint32_t nst = st + (uint32_t)((kb + 1) & 1) * BUF_B;
            cp16(nst + 0*TILE_B,      Ah_p + k0);
            cp16(nst + 0*TILE_B + 16, Ah_p + k0 + 8);
            cp16(nst + 1*TILE_B,      Al_p + k0);
            cp16(nst + 1*TILE_B + 16, Al_p + k0 + 8);
            cp16(nst + 2*TILE_B,      Bh_p + k0);
            cp16(nst + 2*TILE_B + 16, Bh_p + k0 + 8);
            cp16(nst + 3*TILE_B,      Bl_p + k0);
            cp16(nst + 3*TILE_B + 16, Bl_p + k0 + 8);
            cp_commit();
            cp_wait<1>();
        } else {
            cp_wait<0>();
        }
        __syncthreads();

        const uint32_t buf = sb + (uint32_t)(kb & 1) * BUF_B;
#pragma unroll
        for (int s = 0; s < 2; s++) {
            uint32_t a_hi[4][4], a_lo[4][4], b_hi[4][2], b_lo[4][2];
#pragma unroll
            for (int mt = 0; mt < 4; mt++) {
                const uint32_t off = (uint32_t)(a_row + mt * 16) * (LDS_ * 2) + a_colb + s * 32;
                ldsm_x4(a_hi[mt], buf + 0 * TILE_B + off);
                ldsm_x4(a_lo[mt], buf + 1 * TILE_B + off);
            }
#pragma unroll
            for (int p = 0; p < 2; p++) {
                const uint32_t off = (uint32_t)(b_row + p * 16) * (LDS_ * 2) + b_colb + s * 32;
                uint32_t th[4], tl[4];
                ldsm_x4(th, buf + 2 * TILE_B + off);
                ldsm_x4(tl, buf + 3 * TILE_B + off);
                b_hi[2*p][0] = th[0]; b_hi[2*p][1] = th[1];
                b_hi[2*p+1][0] = th[2]; b_hi[2*p+1][1] = th[3];
                b_lo[2*p][0] = tl[0]; b_lo[2*p][1] = tl[1];
                b_lo[2*p+1][0] = tl[2]; b_lo[2*p+1][1] = tl[3];
            }
#pragma unroll
            for (int mt = 0; mt < 4; mt++)
#pragma unroll
                for (int nt = 0; nt < 4; nt++) {
                    mma_bf16(acc[mt][nt], a_hi[mt], b_hi[nt]);
                    mma_bf16(acc[mt][nt], a_lo[mt], b_hi[nt]);
                    mma_bf16(acc[mt][nt], a_hi[mt], b_lo[nt]);
                }
        }
        __syncthreads();
    }

    const int group = lane >> 2, tg = lane & 3;
#pragma unroll
    for (int mt = 0; mt < 4; mt++) {
#pragma unroll
        for (int nt = 0; nt < 4; nt++) {
#pragma unroll
            for (int rp = 0; rp < 2; rp++) {
                const int row = row0 + warp_m * 64 + mt * 16 + group + rp * 8;
                const int lcol = warp_n * 32 + nt * 8 + tg * 2;
                const float v0 = acc[mt][nt][rp * 2 + 0] + s_bias[lcol];
                const float v1 = acc[mt][nt][rp * 2 + 1] + s_bias[lcol + 1];
                if (MODE == 0) {
                    C[(size_t)row * D_ + col0 + lcol] = v0;
                    C[(size_t)row * D_ + col0 + lcol + 1] = v1;
                } else {
                    const int b = row >> 10;
                    const int n = row & (N_ - 1);
                    const int col = col0 + lcol;
                    const int h = col >> 6;
                    const int dh = col & (DH_ - 1);
                    const size_t idx = (((size_t)b * H_ + h) * N_ + n) * DH_ + dh;
                    __nv_bfloat16 h0 = __float2bfloat16(v0);
                    __nv_bfloat16 h1 = __float2bfloat16(v1);
                    __nv_bfloat16 l0 = __float2bfloat16(v0 - __bfloat162float(h0));
                    __nv_bfloat16 l1 = __float2bfloat16(v1 - __bfloat162float(h1));
                    *(__nv_bfloat162*)(Chi + idx) = __nv_bfloat162(h0, h1);
                    *(__nv_bfloat162*)(Clo + idx) = __nv_bfloat162(l0, l1);
                }
            }
        }
    }
}

// ===========================================================================
// Mask dtype detection (unchanged)
// ===========================================================================
__global__ void detect_mask_kind(const unsigned char* __restrict__ m) {
    __shared__ int has_gt1, has_mis;
    if (threadIdx.x == 0) { has_gt1 = 0; has_mis = 0; }
    __syncthreads();
    int lg = 0, lm = 0;
    for (int i = threadIdx.x * 16; i < 65536; i += blockDim.x * 16) {
        uint4 v = *(const uint4*)(m + i);
        unsigned int w[4] = {v.x, v.y, v.z, v.w};
#pragma unroll
        for (int j = 0; j < 4; j++) {
#pragma unroll
            for (int b = 0; b < 4; b++) {
                unsigned int byte = (w[j] >> (8 * b)) & 0xFFu;
                int pos = i + j * 4 + b;
                if (byte > 1u) lg = 1;
                if (byte != 0u && (pos & 3)) lm = 1;
            }
        }
    }
    if (lg) atomicOr(&has_gt1, 1);
    if (lm) atomicOr(&has_mis, 1);
    __syncthreads();
    if (threadIdx.x == 0) g_mask4 = (has_gt1 || !has_mis) ? 1 : 0;
}

// ===========================================================================
// FLASH ATTENTION: per CTA = 128 q rows x one bh. Online softmax, P staged
// in smem as bf16 hi/lo, acc = P @ v. Writes attn (bf16 hi/lo) + row stats.
// Scores/weights never touch gmem here.
// ===========================================================================
#define FQ_B   18432            // 128 rows x 144B (72 bf16 padded)
#define FK_B   9216             // 64 rows x 144B
#define FKV_B  (4 * FK_B)       // k_hi,k_lo,v_hi,v_lo per stage = 36864
#define FP_OFF (2 * FQ_B + 2 * FKV_B)   // 110592
#define FS_TOT (FP_OFF + 2 * FQ_B)      // 147456

__global__ void __launch_bounds__(256, 1) flash_attn(const unsigned char* __restrict__ maskp) {
    extern __shared__ char smem[];
    __shared__ float s_red[128][2];
    __shared__ float s_sum[128][2];
    const int tid = threadIdx.x;
    const int wid = tid >> 5;
    const int lane = tid & 31;
    const int wm = wid >> 1;          // 0..3: 32 rows
    const int wn = wid & 1;           // 0..1: 32 cols (S) / 32 dh (AV)
    const int bh = blockIdx.y;
    const int row0 = blockIdx.x * 128;
    const int group = lane >> 2, tg = lane & 3;
    const uint32_t sb = smem_u32(smem);

    // load q strip (hi/lo)
    {
        const int r = tid >> 1, half = tid & 1;
        const size_t qsrc = (size_t)bh * N_ * DH_ + (size_t)(row0 + r) * DH_ + half * 32;
        const uint32_t dst = (uint32_t)r * 144 + (uint32_t)half * 64;
#pragma unroll
        for (int j = 0; j < 4; j++) {
            *(uint4*)(smem + 0*FQ_B + dst + j*16) = *(const uint4*)(g_pjh[0] + qsrc + j*8);
            *(uint4*)(smem + 1*FQ_B + dst + j*16) = *(const uint4*)(g_pjl[0] + qsrc + j*8);
        }
    }

    const __nv_bfloat16* khb = g_pjh[1] + (size_t)bh * N_ * DH_;
    const __nv_bfloat16* klb = g_pjl[1] + (size_t)bh * N_ * DH_;
    const __nv_bfloat16* vhb = g_pjh[2] + (size_t)bh * N_ * DH_;
    const __nv_bfloat16* vlb = g_pjl[2] + (size_t)bh * N_ * DH_;
    const int vr = tid >> 2, vq = tid & 3;
    const uint32_t kv_dst = (uint32_t)vr * 144 + (uint32_t)vq * 32;
    const uint32_t kvbase = sb + 2 * FQ_B;

    // stage kv block 0
    {
        const size_t src = (size_t)vr * DH_ + vq * 16;
        cp16(kvbase + 0*FK_B + kv_dst,      khb + src);
        cp16(kvbase + 0*FK_B + kv_dst + 16, khb + src + 8);
        cp16(kvbase + 1*FK_B + kv_dst,      klb + src);
        cp16(kvbase + 1*FK_B + kv_dst + 16, klb + src + 8);
        cp16(kvbase + 2*FK_B + kv_dst,      vhb + src);
        cp16(kvbase + 2*FK_B + kv_dst + 16, vhb + src + 8);
        cp16(kvbase + 3*FK_B + kv_dst,      vlb + src);
        cp16(kvbase + 3*FK_B + kv_dst + 16, vlb + src + 8);
        cp_commit();
    }

    const int seg = lane >> 3, l7 = lane & 7;
    const int a_row = wm * 32 + (seg & 1) * 8 + l7;        // + mt*16
    const uint32_t a_colb = (((seg >> 1) & 1) * 8) * 2;    // + s*32
    const int b_row = wn * 32 + ((seg >> 1) & 1) * 8 + l7; // + p*16
    const uint32_t b_colb = ((seg & 1) * 8) * 2;
    const int l15 = lane & 15;
    const uint32_t v_colb = (uint32_t)(wn * 32) * 2 + (lane >> 4) * 16;

    float m_run[2][2], s_run[2][2];
#pragma unroll
    for (int a = 0; a < 2; a++)
#pragma unroll
        for (int b = 0; b < 2; b++) { m_run[a][b] = -3.0e38f; s_run[a][b] = 0.0f; }
    float acc[2][4][4] = {};
    const int m4 = g_mask4;
    const unsigned int* mask32 = (const unsigned int*)maskp;

    for (int kb = 0; kb < 16; kb++) {
        if (kb + 1 < 16) {
            const uint32_t nb = kvbase + (uint32_t)((kb + 1) & 1) * FKV_B;
            const size_t src = (size_t)((kb + 1) * 64 + vr) * DH_ + vq * 16;
            cp16(nb + 0*FK_B + kv_dst,      khb + src);
            cp16(nb + 0*FK_B + kv_dst + 16, khb + src + 8);
            cp16(nb + 1*FK_B + kv_dst,      klb + src);
            cp16(nb + 1*FK_B + kv_dst + 16, klb + src + 8);
            cp16(nb + 2*FK_B + kv_dst,      vhb + src);
            cp16(nb + 2*FK_B + kv_dst + 16, vhb + src + 8);
            cp16(nb + 3*FK_B + kv_dst,      vlb + src);
            cp16(nb + 3*FK_B + kv_dst + 16, vlb + src + 8);
            cp_commit();
            cp_wait<1>();
        } else {
            cp_wait<0>();
        }
        __syncthreads();
        const uint32_t kv = kvbase + (uint32_t)(kb & 1) * FKV_B;

        // ---- S = q @ k^T (128 x 64), bf16x3 ----
        float sacc[2][4][4] = {};
#pragma unroll
        for (int s = 0; s < 4; s++) {
            uint32_t ah[2][4], al_[2][4], bh_[4][2], bl_[4][2];
#pragma unroll
            for (int mt = 0; mt < 2; mt++) {
                const uint32_t off = (uint32_t)(a_row + mt * 16) * 144 + a_colb + s * 32;
                ldsm_x4(ah[mt], sb + 0*FQ_B + off);
                ldsm_x4(al_[mt], sb + 1*FQ_B + off);
            }
#pragma unroll
            for (int p = 0; p < 2; p++) {
                const uint32_t off = (uint32_t)(b_row + p * 16) * 144 + b_colb + s * 32;
                uint32_t th[4], tl[4];
                ldsm_x4(th, kv + 0*FK_B + off);
                ldsm_x4(tl, kv + 1*FK_B + off);
                bh_[2*p][0] = th[0]; bh_[2*p][1] = th[1];
                bh_[2*p+1][0] = th[2]; bh_[2*p+1][1] = th[3];
                bl_[2*p][0] = tl[0]; bl_[2*p][1] = tl[1];
                bl_[2*p+1][0] = tl[2]; bl_[2*p+1][1] = tl[3];
            }
#pragma unroll
            for (int mt = 0; mt < 2; mt++)
#pragma unroll
                for (int nt = 0; nt < 4; nt++) {
                    mma_bf16(sacc[mt][nt], ah[mt], bh_[nt]);
                    mma_bf16(sacc[mt][nt], al_[mt], bh_[nt]);
                    mma_bf16(sacc[mt][nt], ah[mt], bl_[nt]);
                }
        }

        // ---- mask + scale; per-slot running max ----
        float tmax[2][2] = {{-3.0e38f, -3.0e38f}, {-3.0e38f, -3.0e38f}};
#pragma unroll
        for (int mt = 0; mt < 2; mt++)
#pragma unroll
            for (int nt = 0; nt < 4; nt++)
#pragma unroll
                for (int rg = 0; rg < 4; rg++) {
                    const int row = row0 + wm * 32 + mt * 16 + group + (rg >> 1) * 8;
                    const int col = kb * 64 + wn * 32 + nt * 8 + tg * 2 + (rg & 1);
                    const size_t idx = ((size_t)bh * N_ + row) * N_ + col;
                    const bool mk = m4 ? (mask32[idx] != 0u) : (maskp[idx] != 0);
                    const float v = mk ? -1e10f : sacc[mt][nt][rg] * 0.125f;
                    sacc[mt][nt][rg] = v;
                    tmax[mt][rg >> 1] = fmaxf(tmax[mt][rg >> 1], v);
                }
#pragma unroll
        for (int o = 1; o <= 2; o <<= 1)
#pragma unroll
            for (int mt = 0; mt < 2; mt++)
#pragma unroll
                for (int hf = 0; hf < 2; hf++)
                    tmax[mt][hf] = fmaxf(tmax[mt][hf], __shfl_xor_sync(~0u, tmax[mt][hf], o));
        if (tg == 0)
#pragma unroll
            for (int mt = 0; mt < 2; mt++)
#pragma unroll
                for (int hf = 0; hf < 2; hf++)
                    s_red[wm * 32 + mt * 16 + group + hf * 8][wn] = tmax[mt][hf];
        __syncthreads();

        // ---- rescale acc, exp, stage P (bf16 hi/lo), block sum ----
        float bsum[2][2] = {};
#pragma unroll
        for (int mt = 0; mt < 2; mt++)
#pragma unroll
            for (int hf = 0; hf < 2; hf++) {
                const int rl = wm * 32 + mt * 16 + group + hf * 8;
                const float mn = fmaxf(m_run[mt][hf], fmaxf(s_red[rl][0], s_red[rl][1]));
                const float f = __expf(m_run[mt][hf] - mn);
                m_run[mt][hf] = mn;
                s_run[mt][hf] *= f;
#pragma unroll
                for (int nt = 0; nt < 4; nt++) {
                    acc[mt][nt][hf * 2 + 0] *= f;
                    acc[mt][nt][hf * 2 + 1] *= f;
                    const float p0 = __expf(sacc[mt][nt][hf * 2 + 0] - mn);
                    const float p1 = __expf(sacc[mt][nt][hf * 2 + 1] - mn);
                    bsum[mt][hf] += p0 + p1;
                    __nv_bfloat16 h0 = __float2bfloat16(p0);
                    __nv_bfloat16 h1 = __float2bfloat16(p1);
                    __nv_bfloat16 l0 = __float2bfloat16(p0 - __bfloat162float(h0));
                    __nv_bfloat16 l1 = __float2bfloat16(p1 - __bfloat162float(h1));
                    const uint32_t paddr = (uint32_t)rl * 144 + (uint32_t)(wn * 32 + nt * 8 + tg * 2) * 2;
                    *(__nv_bfloat162*)(smem + FP_OFF + paddr)        = __nv_bfloat162(h0, h1);
                    *(__nv_bfloat162*)(smem + FP_OFF + FQ_B + paddr) = __nv_bfloat162(l0, l1);
                }
            }
#pragma unroll
        for (int o = 1; o <= 2; o <<= 1)
#pragma unroll
            for (int mt = 0; mt < 2; mt++)
#pragma unroll
                for (int hf = 0; hf < 2; hf++)
                    bsum[mt][hf] += __shfl_xor_sync(~0u, bsum[mt][hf], o);
        if (tg == 0)
#pragma unroll
            for (int mt = 0; mt < 2; mt++)
#pragma unroll
                for (int hf = 0; hf < 2; hf++)
                    s_sum[wm * 32 + mt * 16 + group + hf * 8][wn] = bsum[mt][hf];
        __syncthreads();
#pragma unroll
        for (int mt = 0; mt < 2; mt++)
#pragma unroll
            for (int hf = 0; hf < 2; hf++) {
                const int rl = wm * 32 + mt * 16 + group + hf * 8;
                s_run[mt][hf] += s_sum[rl][0] + s_sum[rl][1];
            }

        // ---- acc += P @ v (128 x 64), bf16x3 ----
#pragma unroll
        for (int s = 0; s < 4; s++) {
            uint32_t ph[2][4], pl[2][4], vh_[4][2], vl_[4][2];
#pragma unroll
            for (int mt = 0; mt < 2; mt++) {
                const uint32_t off = (uint32_t)(a_row + mt * 16) * 144 + a_colb + s * 32;
                ldsm_x4(ph[mt], sb + FP_OFF + off);
                ldsm_x4(pl[mt], sb + FP_OFF + FQ_B + off);
            }
#pragma unroll
            for (int p = 0; p < 2; p++) {
                const uint32_t off = (uint32_t)(s * 16 + l15) * 144 + v_colb + p * 32;
                uint32_t th[4], tl[4];
                ldsm_x4_t(th, kv + 2*FK_B + off);
                ldsm_x4_t(tl, kv + 3*FK_B + off);
                vh_[2*p][0] = th[0]; vh_[2*p][1] = th[1];
                vh_[2*p+1][0] = th[2]; vh_[2*p+1][1] = th[3];
                vl_[2*p][0] = tl[0]; vl_[2*p][1] = tl[1];
                vl_[2*p+1][0] = tl[2]; vl_[2*p+1][1] = tl[3];
            }
#pragma unroll
            for (int mt = 0; mt < 2; mt++)
#pragma unroll
                for (int nt = 0; nt < 4; nt++) {
                    mma_bf16(acc[mt][nt], ph[mt], vh_[nt]);
                    mma_bf16(acc[mt][nt], pl[mt], vh_[nt]);
                    mma_bf16(acc[mt][nt], ph[mt], vl_[nt]);
                }
        }
        __syncthreads();   // P + kv consumed before next-iter overwrite
    }

    // epilogue: normalize, write attn (bf16 hi/lo) + row stats
    const int b = bh >> 4;
    const int h = bh & (H_ - 1);
#pragma unroll
    for (int mt = 0; mt < 2; mt++)
#pragma unroll
        for (int hf = 0; hf < 2; hf++) {
            const int rl = wm * 32 + mt * 16 + group + hf * 8;
            const float inv = 1.0f / s_run[mt][hf];
            if (wn == 0 && tg == 0) {
                g_rmax[(size_t)bh * N_ + row0 + rl] = m_run[mt][hf];
                g_rinv[(size_t)bh * N_ + row0 + rl] = inv;
            }
#pragma unroll
            for (int nt = 0; nt < 4; nt++) {
                const int dh = wn * 32 + nt * 8 + tg * 2;
                const float v0 = acc[mt][nt][hf * 2 + 0] * inv;
                const float v1 = acc[mt][nt][hf * 2 + 1] * inv;
                const size_t idx = ((size_t)b * N_ + row0 + rl) * D_ + h * DH_ + dh;
                __nv_bfloat16 h0 = __float2bfloat16(v0);
                __nv_bfloat16 h1 = __float2bfloat16(v1);
                __nv_bfloat16 l0 = __float2bfloat16(v0 - __bfloat162float(h0));
                __nv_bfloat16 l1 = __float2bfloat16(v1 - __bfloat162float(h1));
                *(__nv_bfloat162*)(g_ah + idx) = __nv_bfloat162(h0, h1);
                *(__nv_bfloat162*)(g_al + idx) = __nv_bfloat162(l0, l1);
            }
        }
}

// ===========================================================================
// Weights finalize: recompute S (identical mma order), apply exp with stats,
// write normalized fp32 weights to d_out. 128x128 tile per CTA.
// ===========================================================================
#define LDQ  72
#define QT_B (128 * LDQ * 2)

__global__ void __launch_bounds__(256, 1) finalize_weights(const unsigned char* __restrict__ maskp,
                                                           float* __restrict__ wout) {
    extern __shared__ char smem[];
    __shared__ float s_m[128];
    __shared__ float s_i[128];
    const int tid = threadIdx.x;
    const int wid = tid >> 5;
    const int lane = tid & 31;
    const int warp_m = wid >> 2;
    const int warp_n = wid & 3;
    const int bh = blockIdx.z;
    const int row0 = blockIdx.y * 128;
    const int col0 = blockIdx.x * 128;

    if (tid < 128) {
        s_m[tid] = g_rmax[(size_t)bh * N_ + row0 + tid];
        s_i[tid] = g_rinv[(size_t)bh * N_ + row0 + tid];
    }

    const int r = tid >> 1;
    const int half = tid & 1;
    const size_t qsrc = (size_t)bh * N_ * DH_ + (size_t)(row0 + r) * DH_ + half * 32;
    const size_t ksrc = (size_t)bh * N_ * DH_ + (size_t)(col0 + r) * DH_ + half * 32;
    const uint32_t dst = (uint32_t)r * (LDQ * 2) + (uint32_t)half * 64;
#pragma unroll
    for (int j = 0; j < 4; j++) {
        *(uint4*)(smem + 0*QT_B + dst + j*16) = *(const uint4*)(g_pjh[0] + qsrc + j*8);
        *(uint4*)(smem + 1*QT_B + dst + j*16) = *(const uint4*)(g_pjl[0] + qsrc + j*8);
        *(uint4*)(smem + 2*QT_B + dst + j*16) = *(const uint4*)(g_pjh[1] + ksrc + j*8);
        *(uint4*)(smem + 3*QT_B + dst + j*16) = *(const uint4*)(g_pjl[1] + ksrc + j*8);
    }
    __syncthreads();

    const uint32_t sb = smem_u32(smem);
    const int seg = lane >> 3, l7 = lane & 7;
    const int a_row = warp_m * 64 + (seg & 1) * 8 + l7;
    const int a_colb = (((seg >> 1) & 1) * 8) * 2;
    const int b_row = warp_n * 32 + ((seg >> 1) & 1) * 8 + l7;
    const int b_colb = ((seg & 1) * 8) * 2;

    float acc[4][4][4] = {};
#pragma unroll
    for (int s = 0; s < 4; s++) {
        uint32_t a_hi[4][4], a_lo[4][4], b_hi[4][2], b_lo[4][2];
#pragma unroll
        for (int mt = 0; mt < 4; mt++) {
            const uint32_t off = (uint32_t)(a_row + mt * 16) * (LDQ * 2) + a_colb + s * 32;
            ldsm_x4(a_hi[mt], sb + 0 * QT_B + off);
            ldsm_x4(a_lo[mt], sb + 1 * QT_B + off);
        }
#pragma unroll
        for (int p = 0; p < 2; p++) {
            const uint32_t off = (uint32_t)(b_row + p * 16) * (LDQ * 2) + b_colb + s * 32;
            uint32_t th[4], tl[4];
            ldsm_x4(th, sb + 2 * QT_B + off);
            ldsm_x4(tl, sb + 3 * QT_B + off);
            b_hi[2*p][0] = th[0]; b_hi[2*p][1] = th[1];
            b_hi[2*p+1][0] = th[2]; b_hi[2*p+1][1] = th[3];
            b_lo[2*p][0] = tl[0]; b_lo[2*p][1] = tl[1];
            b_lo[2*p+1][0] = tl[2]; b_lo[2*p+1][1] = tl[3];
        }
#pragma unroll
        for (int mt = 0; mt < 4; mt++)
#pragma unroll
            for (int nt = 0; nt < 4; nt++) {
                mma_bf16(acc[mt][nt], a_hi[mt], b_hi[nt]);
                mma_bf16(acc[mt][nt], a_lo[mt], b_hi[nt]);
                mma_bf16(acc[mt][nt], a_hi[mt], b_lo[nt]);
            }
    }

    const int group = lane >> 2, tg = lane & 3;
    const int m4 = g_mask4;
    const unsigned int* mask32 = (const unsigned int*)maskp;
#pragma unroll
    for (int mt = 0; mt < 4; mt++)
#pragma unroll
        for (int nt = 0; nt < 4; nt++)
#pragma unroll
            for (int rg = 0; rg < 4; rg++) {
                const int rl = warp_m * 64 + mt * 16 + group + (rg >> 1) * 8;
                const int row = row0 + rl;
                const int col = col0 + warp_n * 32 + nt * 8 + tg * 2 + (rg & 1);
                const size_t idx = ((size_t)bh * N_ + row) * N_ + col;
                const bool mk = m4 ? (mask32[idx] != 0u) : (maskp[idx] != 0);
                const float sc = mk ? -1e10f : acc[mt][nt][rg] * 0.125f;
                wout[idx] = __expf(sc - s_m[rl]) * s_i[rl];
            }
}

// ===========================================================================
extern "C" void kernel_launch(void* const* d_in, const int* in_sizes, int n_in,
                              void* d_out, int out_size) {
    const float* Q  = (const float*)d_in[0];
    const float* K  = (const float*)d_in[1];
    const float* V  = (const float*)d_in[2];
    const unsigned char* mask = (const unsigned char*)d_in[3];
    const float* Wq = (const float*)d_in[4];
    const float* bq = (const float*)d_in[5];
    const float* Wk = (const float*)d_in[6];
    const float* bk = (const float*)d_in[7];
    const float* Wv = (const float*)d_in[8];
    const float* bv = (const float*)d_in[9];
    const float* Wo = (const float*)d_in[10];
    const float* bo = (const float*)d_in[11];

    float* xout = (float*)d_out;
    float* wout = xout + (size_t)M_ * D_;

    __nv_bfloat16 *pjh, *pjl, *inh, *inl, *wth, *wtl, *ah, *al;
    cudaGetSymbolAddress((void**)&pjh, g_pjh);
    cudaGetSymbolAddress((void**)&pjl, g_pjl);
    cudaGetSymbolAddress((void**)&inh, g_inh);
    cudaGetSymbolAddress((void**)&inl, g_inl);
    cudaGetSymbolAddress((void**)&wth, g_wth);
    cudaGetSymbolAddress((void**)&wtl, g_wtl);
    cudaGetSymbolAddress((void**)&ah, g_ah);
    cudaGetSymbolAddress((void**)&al, g_al);

    const int gemm_smem = 2 * BUF_B;
    const int flash_smem = FS_TOT;
    const int fin_smem = 4 * QT_B;
    cudaFuncSetAttribute(gemm_mma<0>, cudaFuncAttributeMaxDynamicSharedMemorySize, gemm_smem);
    cudaFuncSetAttribute(gemm_mma<1>, cudaFuncAttributeMaxDynamicSharedMemorySize, gemm_smem);
    cudaFuncSetAttribute(flash_attn, cudaFuncAttributeMaxDynamicSharedMemorySize, flash_smem);
    cudaFuncSetAttribute(finalize_weights, cudaFuncAttributeMaxDynamicSharedMemorySize, fin_smem);

    detect_mask_kind<<<1, 256>>>(mask);

    const size_t inN = (size_t)M_ * D_;
    const size_t wN  = (size_t)D_ * D_;
    cvt_hilo<<<(int)(inN / 4 / 256), 256>>>(Q, inh + 0 * inN, inl + 0 * inN, (int)(inN / 4));
    cvt_hilo<<<(int)(inN / 4 / 256), 256>>>(K, inh + 1 * inN, inl + 1 * inN, (int)(inN / 4));
    cvt_hilo<<<(int)(inN / 4 / 256), 256>>>(V, inh + 2 * inN, inl + 2 * inN, (int)(inN / 4));
    Src4 s4; s4.p[0] = Wq; s4.p[1] = Wk; s4.p[2] = Wv; s4.p[3] = Wo;
    cvt_hilo4<<<dim3((int)(wN / 4 / 256), 1, 4), 256>>>(s4, wth, wtl, (int)(wN / 4));

    Bias3 bqkv; bqkv.p[0] = bq; bqkv.p[1] = bk; bqkv.p[2] = bv;
    gemm_mma<1><<<dim3(D_ / 128, M_ / 128, 3), 256, gemm_smem>>>(
        inh, inl, wth, wtl, bqkv, nullptr, pjh, pjl);

    flash_attn<<<dim3(N_ / 128, BH_), 256, flash_smem>>>(mask);
    finalize_weights<<<dim3(N_ / 128, N_ / 128, BH_), 256, fin_smem>>>(mask, wout);

    Bias3 bout; bout.p[0] = bo; bout.p[1] = bo; bout.p[2] = bo;
    gemm_mma<0><<<dim3(D_ / 128, M_ / 128, 1), 256, gemm_smem>>>(
        ah, al, wth + 3 * wN, wtl + 3 * wN, bout, xout, nullptr, nullptr);
}

// round 12
// speedup vs baseline: 1.1643x; 1.1643x over previous
#include <cuda_runtime.h>
#include <cuda_bf16.h>
#include <cstdint>

// Problem constants
#define B_   4
#define N_   1024
#define D_   1024
#define H_   16
#define DH_  64
#define M_   (B_ * N_)    // 4096
#define BH_  (B_ * H_)    // 64

// Scratch (allocation-free rule: __device__ globals)
__device__ __nv_bfloat16 g_pjh[3][(size_t)M_ * D_];   // projected q,k,v hi
__device__ __nv_bfloat16 g_pjl[3][(size_t)M_ * D_];   // projected q,k,v lo
__device__ __nv_bfloat16 g_inh[3][(size_t)M_ * D_];
__device__ __nv_bfloat16 g_inl[3][(size_t)M_ * D_];
__device__ __nv_bfloat16 g_wth[4][(size_t)D_ * D_];
__device__ __nv_bfloat16 g_wtl[4][(size_t)D_ * D_];
__device__ __nv_bfloat16 g_wh[(size_t)BH_ * N_ * N_]; // softmaxed weights hi
__device__ __nv_bfloat16 g_wl[(size_t)BH_ * N_ * N_]; // softmaxed weights lo
__device__ __nv_bfloat16 g_ah[(size_t)M_ * D_];
__device__ __nv_bfloat16 g_al[(size_t)M_ * D_];
__device__ int   g_mask4;

struct Bias3 { const float* p[3]; };
struct Src4  { const float* p[4]; };

// ===========================================================================
// Helpers (generic PTX, sm_80+ only)
// ===========================================================================
__device__ __forceinline__ uint32_t smem_u32(const void* p) {
    uint32_t a;
    asm("{ .reg .u64 t; cvta.to.shared.u64 t, %1; cvt.u32.u64 %0, t; }" : "=r"(a) : "l"(p));
    return a;
}
__device__ __forceinline__ void ldsm_x4(uint32_t* r, uint32_t addr) {
    asm volatile("ldmatrix.sync.aligned.m8n8.x4.shared.b16 {%0,%1,%2,%3}, [%4];"
                 : "=r"(r[0]), "=r"(r[1]), "=r"(r[2]), "=r"(r[3]) : "r"(addr));
}
__device__ __forceinline__ void ldsm_x4_t(uint32_t* r, uint32_t addr) {
    asm volatile("ldmatrix.sync.aligned.m8n8.x4.trans.shared.b16 {%0,%1,%2,%3}, [%4];"
                 : "=r"(r[0]), "=r"(r[1]), "=r"(r[2]), "=r"(r[3]) : "r"(addr));
}
__device__ __forceinline__ void mma_bf16(float* c, const uint32_t* a, const uint32_t* b) {
    asm volatile(
        "mma.sync.aligned.m16n8k16.row.col.f32.bf16.bf16.f32 "
        "{%0,%1,%2,%3}, {%4,%5,%6,%7}, {%8,%9}, {%0,%1,%2,%3};"
        : "+f"(c[0]), "+f"(c[1]), "+f"(c[2]), "+f"(c[3])
        : "r"(a[0]), "r"(a[1]), "r"(a[2]), "r"(a[3]), "r"(b[0]), "r"(b[1]));
}
__device__ __forceinline__ void cp16(uint32_t smem, const void* g) {
    asm volatile("cp.async.ca.shared.global [%0], [%1], 16;" :: "r"(smem), "l"(g));
}
__device__ __forceinline__ void cp_commit() { asm volatile("cp.async.commit_group;"); }
template <int N>
__device__ __forceinline__ void cp_wait() { asm volatile("cp.async.wait_group %0;" :: "n"(N)); }

// ===========================================================================
// fp32 -> bf16 hi/lo conversion
// ===========================================================================
__device__ __forceinline__ void cvt_body(const float* __restrict__ src,
                                         __nv_bfloat16* __restrict__ dh,
                                         __nv_bfloat16* __restrict__ dl, int i) {
    float4 v = ((const float4*)src)[i];
    __nv_bfloat16 h0 = __float2bfloat16(v.x), h1 = __float2bfloat16(v.y);
    __nv_bfloat16 h2 = __float2bfloat16(v.z), h3 = __float2bfloat16(v.w);
    __nv_bfloat16 l0 = __float2bfloat16(v.x - __bfloat162float(h0));
    __nv_bfloat16 l1 = __float2bfloat16(v.y - __bfloat162float(h1));
    __nv_bfloat16 l2 = __float2bfloat16(v.z - __bfloat162float(h2));
    __nv_bfloat16 l3 = __float2bfloat16(v.w - __bfloat162float(h3));
    ((__nv_bfloat162*)dh)[i * 2]     = __nv_bfloat162(h0, h1);
    ((__nv_bfloat162*)dh)[i * 2 + 1] = __nv_bfloat162(h2, h3);
    ((__nv_bfloat162*)dl)[i * 2]     = __nv_bfloat162(l0, l1);
    ((__nv_bfloat162*)dl)[i * 2 + 1] = __nv_bfloat162(l2, l3);
}
__global__ void cvt_hilo(const float* __restrict__ src,
                         __nv_bfloat16* __restrict__ dh,
                         __nv_bfloat16* __restrict__ dl, int n4) {
    const int i = blockIdx.x * blockDim.x + threadIdx.x;
    if (i < n4) cvt_body(src, dh, dl, i);
}
__global__ void cvt_hilo4(Src4 s4, __nv_bfloat16* __restrict__ dh,
                          __nv_bfloat16* __restrict__ dl, int n4) {
    const int i = blockIdx.x * blockDim.x + threadIdx.x;
    const int z = blockIdx.z;
    if (i < n4) cvt_body(s4.p[z], dh + (size_t)z * D_ * D_, dl + (size_t)z * D_ * D_, i);
}

// ===========================================================================
// bf16x3 NT GEMM (R6 2-stage, z-batched), occupancy 2.
// ===========================================================================
#define BK_      32
#define LDS_     40
#define TILE_B   (128 * LDS_ * 2)
#define BUF_B    (4 * TILE_B)
#define NUM_KB   (D_ / BK_)

template <int MODE>
__global__ void __launch_bounds__(256, 2) gemm_mma(const __nv_bfloat16* __restrict__ Ah,
                                                   const __nv_bfloat16* __restrict__ Al,
                                                   const __nv_bfloat16* __restrict__ Bh,
                                                   const __nv_bfloat16* __restrict__ Bl,
                                                   Bias3 b3,
                                                   float* __restrict__ C,
                                                   __nv_bfloat16* __restrict__ Chi,
                                                   __nv_bfloat16* __restrict__ Clo) {
    extern __shared__ char smem[];
    __shared__ float s_bias[128];

    const int z = blockIdx.z;
    Ah += (size_t)z * M_ * D_;
    Al += (size_t)z * M_ * D_;
    Bh += (size_t)z * D_ * D_;
    Bl += (size_t)z * D_ * D_;
    const float* bias = b3.p[z];
    if (MODE == 1) { Chi += (size_t)z * M_ * D_; Clo += (size_t)z * M_ * D_; }

    const int tid = threadIdx.x;
    const int wid = tid >> 5;
    const int lane = tid & 31;
    const int warp_m = wid >> 2;
    const int warp_n = wid & 3;
    const int row0 = blockIdx.y * 128;
    const int col0 = blockIdx.x * 128;

    if (tid < 128) s_bias[tid] = bias[col0 + tid];

    const int r  = tid >> 1;
    const int half = tid & 1;
    const __nv_bfloat16* Ah_p = Ah + (size_t)(row0 + r) * D_ + half * 16;
    const __nv_bfloat16* Al_p = Al + (size_t)(row0 + r) * D_ + half * 16;
    const __nv_bfloat16* Bh_p = Bh + (size_t)(col0 + r) * D_ + half * 16;
    const __nv_bfloat16* Bl_p = Bl + (size_t)(col0 + r) * D_ + half * 16;
    const uint32_t sb = smem_u32(smem);
    const uint32_t st = sb + (uint32_t)r * (LDS_ * 2) + (uint32_t)half * 32;

    const int seg = lane >> 3, l7 = lane & 7;
    const int a_row = warp_m * 64 + (seg & 1) * 8 + l7;
    const int a_colb = (((seg >> 1) & 1) * 8) * 2;
    const int b_row = warp_n * 32 + ((seg >> 1) & 1) * 8 + l7;
    const int b_colb = ((seg & 1) * 8) * 2;

    float acc[4][4][4] = {};

    {
        cp16(st + 0*TILE_B,      Ah_p);
        cp16(st + 0*TILE_B + 16, Ah_p + 8);
        cp16(st + 1*TILE_B,      Al_p);
        cp16(st + 1*TILE_B + 16, Al_p + 8);
        cp16(st + 2*TILE_B,      Bh_p);
        cp16(st + 2*TILE_B + 16, Bh_p + 8);
        cp16(st + 3*TILE_B,      Bl_p);
        cp16(st + 3*TILE_B + 16, Bl_p + 8);
        cp_commit();
    }

    for (int kb = 0; kb < NUM_KB; kb++) {
        if (kb + 1 < NUM_KB) {
            const int k0 = (kb + 1) * BK_;
            const uint32_t nst = st + (uint32_t)((kb + 1) & 1) * BUF_B;
            cp16(nst + 0*TILE_B,      Ah_p + k0);
            cp16(nst + 0*TILE_B + 16, Ah_p + k0 + 8);
            cp16(nst + 1*TILE_B,      Al_p + k0);
            cp16(nst + 1*TILE_B + 16, Al_p + k0 + 8);
            cp16(nst + 2*TILE_B,      Bh_p + k0);
            cp16(nst + 2*TILE_B + 16, Bh_p + k0 + 8);
            cp16(nst + 3*TILE_B,      Bl_p + k0);
            cp16(nst + 3*TILE_B + 16, Bl_p + k0 + 8);
            cp_commit();
            cp_wait<1>();
        } else {
            cp_wait<0>();
        }
        __syncthreads();

        const uint32_t buf = sb + (uint32_t)(kb & 1) * BUF_B;
#pragma unroll
        for (int s = 0; s < 2; s++) {
            uint32_t a_hi[4][4], a_lo[4][4], b_hi[4][2], b_lo[4][2];
#pragma unroll
            for (int mt = 0; mt < 4; mt++) {
                const uint32_t off = (uint32_t)(a_row + mt * 16) * (LDS_ * 2) + a_colb + s * 32;
                ldsm_x4(a_hi[mt], buf + 0 * TILE_B + off);
                ldsm_x4(a_lo[mt], buf + 1 * TILE_B + off);
            }
#pragma unroll
            for (int p = 0; p < 2; p++) {
                const uint32_t off = (uint32_t)(b_row + p * 16) * (LDS_ * 2) + b_colb + s * 32;
                uint32_t th[4], tl[4];
                ldsm_x4(th, buf + 2 * TILE_B + off);
                ldsm_x4(tl, buf + 3 * TILE_B + off);
                b_hi[2*p][0] = th[0]; b_hi[2*p][1] = th[1];
                b_hi[2*p+1][0] = th[2]; b_hi[2*p+1][1] = th[3];
                b_lo[2*p][0] = tl[0]; b_lo[2*p][1] = tl[1];
                b_lo[2*p+1][0] = tl[2]; b_lo[2*p+1][1] = tl[3];
            }
#pragma unroll
            for (int mt = 0; mt < 4; mt++)
#pragma unroll
                for (int nt = 0; nt < 4; nt++) {
                    mma_bf16(acc[mt][nt], a_hi[mt], b_hi[nt]);
                    mma_bf16(acc[mt][nt], a_lo[mt], b_hi[nt]);
                    mma_bf16(acc[mt][nt], a_hi[mt], b_lo[nt]);
                }
        }
        __syncthreads();
    }

    const int group = lane >> 2, tg = lane & 3;
#pragma unroll
    for (int mt = 0; mt < 4; mt++) {
#pragma unroll
        for (int nt = 0; nt < 4; nt++) {
#pragma unroll
            for (int rp = 0; rp < 2; rp++) {
                const int row = row0 + warp_m * 64 + mt * 16 + group + rp * 8;
                const int lcol = warp_n * 32 + nt * 8 + tg * 2;
                const float v0 = acc[mt][nt][rp * 2 + 0] + s_bias[lcol];
                const float v1 = acc[mt][nt][rp * 2 + 1] + s_bias[lcol + 1];
                if (MODE == 0) {
                    C[(size_t)row * D_ + col0 + lcol] = v0;
                    C[(size_t)row * D_ + col0 + lcol + 1] = v1;
                } else {
                    const int b = row >> 10;
                    const int n = row & (N_ - 1);
                    const int col = col0 + lcol;
                    const int h = col >> 6;
                    const int dh = col & (DH_ - 1);
                    const size_t idx = (((size_t)b * H_ + h) * N_ + n) * DH_ + dh;
                    __nv_bfloat16 h0 = __float2bfloat16(v0);
                    __nv_bfloat16 h1 = __float2bfloat16(v1);
                    __nv_bfloat16 l0 = __float2bfloat16(v0 - __bfloat162float(h0));
                    __nv_bfloat16 l1 = __float2bfloat16(v1 - __bfloat162float(h1));
                    *(__nv_bfloat162*)(Chi + idx) = __nv_bfloat162(h0, h1);
                    *(__nv_bfloat162*)(Clo + idx) = __nv_bfloat162(l0, l1);
                }
            }
        }
    }
}

// ===========================================================================
// Mask dtype detection (unchanged)
// ===========================================================================
__global__ void detect_mask_kind(const unsigned char* __restrict__ m) {
    __shared__ int has_gt1, has_mis;
    if (threadIdx.x == 0) { has_gt1 = 0; has_mis = 0; }
    __syncthreads();
    int lg = 0, lm = 0;
    for (int i = threadIdx.x * 16; i < 65536; i += blockDim.x * 16) {
        uint4 v = *(const uint4*)(m + i);
        unsigned int w[4] = {v.x, v.y, v.z, v.w};
#pragma unroll
        for (int j = 0; j < 4; j++) {
#pragma unroll
            for (int b = 0; b < 4; b++) {
                unsigned int byte = (w[j] >> (8 * b)) & 0xFFu;
                int pos = i + j * 4 + b;
                if (byte > 1u) lg = 1;
                if (byte != 0u && (pos & 3)) lm = 1;
            }
        }
    }
    if (lg) atomicOr(&has_gt1, 1);
    if (lm) atomicOr(&has_mis, 1);
    __syncthreads();
    if (threadIdx.x == 0) g_mask4 = (has_gt1 || !has_mis) ? 1 : 0;
}

// ===========================================================================
// Scores via mma, bf16x3: writes RAW masked, scaled scores? No — R6 version:
// writes masked, scaled scores to wout (softmax normalizes after). Occ 2.
// ===========================================================================
#define LDQ  72
#define QT_B (128 * LDQ * 2)

__global__ void __launch_bounds__(256, 2) scores_mma(const unsigned char* __restrict__ maskp,
                                                     float* __restrict__ wout) {
    extern __shared__ char smem[];
    const int tid = threadIdx.x;
    const int wid = tid >> 5;
    const int lane = tid & 31;
    const int warp_m = wid >> 2;
    const int warp_n = wid & 3;
    const int bh = blockIdx.z;
    const int row0 = blockIdx.y * 128;
    const int col0 = blockIdx.x * 128;

    const int r = tid >> 1;
    const int half = tid & 1;
    const size_t qsrc = (size_t)bh * N_ * DH_ + (size_t)(row0 + r) * DH_ + half * 32;
    const size_t ksrc = (size_t)bh * N_ * DH_ + (size_t)(col0 + r) * DH_ + half * 32;
    const uint32_t dst = (uint32_t)r * (LDQ * 2) + (uint32_t)half * 64;
#pragma unroll
    for (int j = 0; j < 4; j++) {
        *(uint4*)(smem + 0*QT_B + dst + j*16) = *(const uint4*)(g_pjh[0] + qsrc + j*8);
        *(uint4*)(smem + 1*QT_B + dst + j*16) = *(const uint4*)(g_pjl[0] + qsrc + j*8);
        *(uint4*)(smem + 2*QT_B + dst + j*16) = *(const uint4*)(g_pjh[1] + ksrc + j*8);
        *(uint4*)(smem + 3*QT_B + dst + j*16) = *(const uint4*)(g_pjl[1] + ksrc + j*8);
    }
    __syncthreads();

    const uint32_t sb = smem_u32(smem);
    const int seg = lane >> 3, l7 = lane & 7;
    const int a_row = warp_m * 64 + (seg & 1) * 8 + l7;
    const int a_colb = (((seg >> 1) & 1) * 8) * 2;
    const int b_row = warp_n * 32 + ((seg >> 1) & 1) * 8 + l7;
    const int b_colb = ((seg & 1) * 8) * 2;

    float acc[4][4][4] = {};
#pragma unroll
    for (int s = 0; s < 4; s++) {
        uint32_t a_hi[4][4], a_lo[4][4], b_hi[4][2], b_lo[4][2];
#pragma unroll
        for (int mt = 0; mt < 4; mt++) {
            const uint32_t off = (uint32_t)(a_row + mt * 16) * (LDQ * 2) + a_colb + s * 32;
            ldsm_x4(a_hi[mt], sb + 0 * QT_B + off);
            ldsm_x4(a_lo[mt], sb + 1 * QT_B + off);
        }
#pragma unroll
        for (int p = 0; p < 2; p++) {
            const uint32_t off = (uint32_t)(b_row + p * 16) * (LDQ * 2) + b_colb + s * 32;
            uint32_t th[4], tl[4];
            ldsm_x4(th, sb + 2 * QT_B + off);
            ldsm_x4(tl, sb + 3 * QT_B + off);
            b_hi[2*p][0] = th[0]; b_hi[2*p][1] = th[1];
            b_hi[2*p+1][0] = th[2]; b_hi[2*p+1][1] = th[3];
            b_lo[2*p][0] = tl[0]; b_lo[2*p][1] = tl[1];
            b_lo[2*p+1][0] = tl[2]; b_lo[2*p+1][1] = tl[3];
        }
#pragma unroll
        for (int mt = 0; mt < 4; mt++)
#pragma unroll
            for (int nt = 0; nt < 4; nt++) {
                mma_bf16(acc[mt][nt], a_hi[mt], b_hi[nt]);
                mma_bf16(acc[mt][nt], a_lo[mt], b_hi[nt]);
                mma_bf16(acc[mt][nt], a_hi[mt], b_lo[nt]);
            }
    }

    const int group = lane >> 2, tg = lane & 3;
    const int m4 = g_mask4;
    const unsigned int* mask32 = (const unsigned int*)maskp;
#pragma unroll
    for (int mt = 0; mt < 4; mt++)
#pragma unroll
        for (int nt = 0; nt < 4; nt++)
#pragma unroll
            for (int rg = 0; rg < 4; rg++) {
                const int row = row0 + warp_m * 64 + mt * 16 + group + (rg >> 1) * 8;
                const int col = col0 + warp_n * 32 + nt * 8 + tg * 2 + (rg & 1);
                const size_t idx = ((size_t)bh * N_ + row) * N_ + col;
                const bool masked = m4 ? (mask32[idx] != 0u) : (maskp[idx] != 0);
                wout[idx] = masked ? -1e10f : acc[mt][nt][rg] * 0.125f;
            }
}

// ===========================================================================
// Row softmax; writes fp32 weights + bf16 hi/lo copies (R6 version).
// ===========================================================================
__global__ void __launch_bounds__(256) softmax_rows(float* __restrict__ w) {
    const size_t base = (size_t)blockIdx.x * N_;
    float* p = w + base;
    float4 v = ((float4*)p)[threadIdx.x];

    __shared__ float smax[8];
    __shared__ float ssum[8];
    const int warp = threadIdx.x >> 5, lane = threadIdx.x & 31;

    float m = fmaxf(fmaxf(v.x, v.y), fmaxf(v.z, v.w));
#pragma unroll
    for (int o = 16; o; o >>= 1) m = fmaxf(m, __shfl_xor_sync(~0u, m, o));
    if (lane == 0) smax[warp] = m;
    __syncthreads();
    if (warp == 0) {
        float t = (lane < 8) ? smax[lane] : -3.4e38f;
#pragma unroll
        for (int o = 4; o; o >>= 1) t = fmaxf(t, __shfl_xor_sync(~0u, t, o));
        if (lane == 0) smax[0] = t;
    }
    __syncthreads();
    m = smax[0];

    v.x = __expf(v.x - m); v.y = __expf(v.y - m);
    v.z = __expf(v.z - m); v.w = __expf(v.w - m);
    float s = v.x + v.y + v.z + v.w;
#pragma unroll
    for (int o = 16; o; o >>= 1) s += __shfl_xor_sync(~0u, s, o);
    if (lane == 0) ssum[warp] = s;
    __syncthreads();
    if (warp == 0) {
        float t = (lane < 8) ? ssum[lane] : 0.0f;
#pragma unroll
        for (int o = 4; o; o >>= 1) t += __shfl_xor_sync(~0u, t, o);
        if (lane == 0) ssum[0] = t;
    }
    __syncthreads();
    const float inv = 1.0f / ssum[0];
    v.x *= inv; v.y *= inv; v.z *= inv; v.w *= inv;
    ((float4*)p)[threadIdx.x] = v;

    __nv_bfloat16 h0 = __float2bfloat16(v.x), h1 = __float2bfloat16(v.y);
    __nv_bfloat16 h2 = __float2bfloat16(v.z), h3 = __float2bfloat16(v.w);
    __nv_bfloat16 l0 = __float2bfloat16(v.x - __bfloat162float(h0));
    __nv_bfloat16 l1 = __float2bfloat16(v.y - __bfloat162float(h1));
    __nv_bfloat16 l2 = __float2bfloat16(v.z - __bfloat162float(h2));
    __nv_bfloat16 l3 = __float2bfloat16(v.w - __bfloat162float(h3));
    const size_t off = base + threadIdx.x * 4;
    *(__nv_bfloat162*)(g_wh + off)     = __nv_bfloat162(h0, h1);
    *(__nv_bfloat162*)(g_wh + off + 2) = __nv_bfloat162(h2, h3);
    *(__nv_bfloat162*)(g_wl + off)     = __nv_bfloat162(l0, l1);
    *(__nv_bfloat162*)(g_wl + off + 2) = __nv_bfloat162(l2, l3);
}

// ===========================================================================
// attn = weights @ v via mma, bf16x3 (R6 version), occupancy 2.
// ===========================================================================
#define AT_B   (128 * LDQ * 2)
#define VT_B   (64 * LDQ * 2)
#define AB_B   (2 * AT_B + 2 * VT_B)
#define NKB_A  (N_ / 64)

__global__ void __launch_bounds__(256, 2) attn_mma(void) {
    extern __shared__ char smem[];
    const int tid = threadIdx.x;
    const int wid = tid >> 5;
    const int lane = tid & 31;
    const int warp_m = wid >> 1;
    const int warp_n = wid & 1;
    const int bh = blockIdx.y;
    const int row0 = blockIdx.x * 128;

    const __nv_bfloat16* whb = g_wh + (size_t)bh * N_ * N_;
    const __nv_bfloat16* wlb = g_wl + (size_t)bh * N_ * N_;
    const __nv_bfloat16* vhb = g_pjh[2] + (size_t)bh * N_ * DH_;
    const __nv_bfloat16* vlb = g_pjl[2] + (size_t)bh * N_ * DH_;

    const int ar = tid >> 1, ahalf = tid & 1;
    const uint32_t a_dst = (uint32_t)ar * (LDQ * 2) + (uint32_t)ahalf * 64;
    const int vr = tid >> 2, vq = tid & 3;
    const uint32_t v_dst = (uint32_t)vr * (LDQ * 2) + (uint32_t)vq * 32;

    {
        const size_t asrc = (size_t)(row0 + ar) * N_ + ahalf * 32;
        const size_t vsrc = (size_t)vr * DH_ + vq * 16;
#pragma unroll
        for (int j = 0; j < 4; j++) {
            *(uint4*)(smem + 0*AT_B + a_dst + j*16) = *(const uint4*)(whb + asrc + j*8);
            *(uint4*)(smem + 1*AT_B + a_dst + j*16) = *(const uint4*)(wlb + asrc + j*8);
        }
#pragma unroll
        for (int j = 0; j < 2; j++) {
            *(uint4*)(smem + 2*AT_B + 0*VT_B + v_dst + j*16) = *(const uint4*)(vhb + vsrc + j*8);
            *(uint4*)(smem + 2*AT_B + 1*VT_B + v_dst + j*16) = *(const uint4*)(vlb + vsrc + j*8);
        }
    }
    __syncthreads();

    const uint32_t sb = smem_u32(smem);
    const int l15 = lane & 15;
    const int a_row = warp_m * 32 + l15;
    const int a_colb = (lane >> 4) * 16;
    const int v_row = l15;
    const int v_colb = (warp_n * 32) * 2 + (lane >> 4) * 16;

    float acc[2][4][4] = {};
    uint4 pa[8], pv[4];

    for (int kb = 0; kb < NKB_A; kb++) {
        if (kb + 1 < NKB_A) {
            const int k0 = (kb + 1) * 64;
            const size_t asrc = (size_t)(row0 + ar) * N_ + k0 + ahalf * 32;
            const size_t vsrc = (size_t)(k0 + vr) * DH_ + vq * 16;
#pragma unroll
            for (int j = 0; j < 4; j++) {
                pa[j]     = *(const uint4*)(whb + asrc + j*8);
                pa[4 + j] = *(const uint4*)(wlb + asrc + j*8);
            }
#pragma unroll
            for (int j = 0; j < 2; j++) {
                pv[j]     = *(const uint4*)(vhb + vsrc + j*8);
                pv[2 + j] = *(const uint4*)(vlb + vsrc + j*8);
            }
        }

        const uint32_t buf = sb + (uint32_t)(kb & 1) * AB_B;
#pragma unroll
        for (int s = 0; s < 4; s++) {
            uint32_t a_hi[2][4], a_lo[2][4], b_hi[4][2], b_lo[4][2];
#pragma unroll
            for (int mt = 0; mt < 2; mt++) {
                const uint32_t off = (uint32_t)(a_row + mt * 16) * (LDQ * 2) + a_colb + s * 32;
                ldsm_x4(a_hi[mt], buf + 0 * AT_B + off);
                ldsm_x4(a_lo[mt], buf + 1 * AT_B + off);
            }
#pragma unroll
            for (int p = 0; p < 2; p++) {
                const uint32_t off = (uint32_t)(s * 16 + v_row) * (LDQ * 2) + v_colb + p * 32;
                uint32_t th[4], tl[4];
                ldsm_x4_t(th, buf + 2 * AT_B + 0 * VT_B + off);
                ldsm_x4_t(tl, buf + 2 * AT_B + 1 * VT_B + off);
                b_hi[2*p][0] = th[0]; b_hi[2*p][1] = th[1];
                b_hi[2*p+1][0] = th[2]; b_hi[2*p+1][1] = th[3];
                b_lo[2*p][0] = tl[0]; b_lo[2*p][1] = tl[1];
                b_lo[2*p+1][0] = tl[2]; b_lo[2*p+1][1] = tl[3];
            }
#pragma unroll
            for (int mt = 0; mt < 2; mt++)
#pragma unroll
                for (int nt = 0; nt < 4; nt++) {
                    mma_bf16(acc[mt][nt], a_hi[mt], b_hi[nt]);
                    mma_bf16(acc[mt][nt], a_lo[mt], b_hi[nt]);
                    mma_bf16(acc[mt][nt], a_hi[mt], b_lo[nt]);
                }
        }

        if (kb + 1 < NKB_A) {
            char* base = smem + ((kb + 1) & 1) * AB_B;
#pragma unroll
            for (int j = 0; j < 4; j++) {
                *(uint4*)(base + 0*AT_B + a_dst + j*16) = pa[j];
                *(uint4*)(base + 1*AT_B + a_dst + j*16) = pa[4 + j];
            }
#pragma unroll
            for (int j = 0; j < 2; j++) {
                *(uint4*)(base + 2*AT_B + 0*VT_B + v_dst + j*16) = pv[j];
                *(uint4*)(base + 2*AT_B + 1*VT_B + v_dst + j*16) = pv[2 + j];
            }
        }
        __syncthreads();
    }

    const int b = bh >> 4;
    const int h = bh & (H_ - 1);
    const int group = lane >> 2, tg = lane & 3;
#pragma unroll
    for (int mt = 0; mt < 2; mt++)
#pragma unroll
        for (int nt = 0; nt < 4; nt++)
#pragma unroll
            for (int rp = 0; rp < 2; rp++) {
                const int n = row0 + warp_m * 32 + mt * 16 + group + rp * 8;
                const int dh = warp_n * 32 + nt * 8 + tg * 2;
                const float v0 = acc[mt][nt][rp * 2 + 0];
                const float v1 = acc[mt][nt][rp * 2 + 1];
                const size_t idx = ((size_t)b * N_ + n) * D_ + h * DH_ + dh;
                __nv_bfloat16 h0 = __float2bfloat16(v0);
                __nv_bfloat16 h1 = __float2bfloat16(v1);
                __nv_bfloat16 l0 = __float2bfloat16(v0 - __bfloat162float(h0));
                __nv_bfloat16 l1 = __float2bfloat16(v1 - __bfloat162float(h1));
                *(__nv_bfloat162*)(g_ah + idx) = __nv_bfloat162(h0, h1);
                *(__nv_bfloat162*)(g_al + idx) = __nv_bfloat162(l0, l1);
            }
}

// ===========================================================================
extern "C" void kernel_launch(void* const* d_in, const int* in_sizes, int n_in,
                              void* d_out, int out_size) {
    const float* Q  = (const float*)d_in[0];
    const float* K  = (const float*)d_in[1];
    const float* V  = (const float*)d_in[2];
    const unsigned char* mask = (const unsigned char*)d_in[3];
    const float* Wq = (const float*)d_in[4];
    const float* bq = (const float*)d_in[5];
    const float* Wk = (const float*)d_in[6];
    const float* bk = (const float*)d_in[7];
    const float* Wv = (const float*)d_in[8];
    const float* bv = (const float*)d_in[9];
    const float* Wo = (const float*)d_in[10];
    const float* bo = (const float*)d_in[11];

    float* xout = (float*)d_out;
    float* wout = xout + (size_t)M_ * D_;

    __nv_bfloat16 *pjh, *pjl, *inh, *inl, *wth, *wtl, *ah, *al;
    cudaGetSymbolAddress((void**)&pjh, g_pjh);
    cudaGetSymbolAddress((void**)&pjl, g_pjl);
    cudaGetSymbolAddress((void**)&inh, g_inh);
    cudaGetSymbolAddress((void**)&inl, g_inl);
    cudaGetSymbolAddress((void**)&wth, g_wth);
    cudaGetSymbolAddress((void**)&wtl, g_wtl);
    cudaGetSymbolAddress((void**)&ah, g_ah);
    cudaGetSymbolAddress((void**)&al, g_al);

    const int gemm_smem = 2 * BUF_B;       // 81920
    const int scores_smem = 4 * QT_B;      // 73728
    const int attn_smem = 2 * AB_B;        // 110592
    cudaFuncSetAttribute(gemm_mma<0>, cudaFuncAttributeMaxDynamicSharedMemorySize, gemm_smem);
    cudaFuncSetAttribute(gemm_mma<1>, cudaFuncAttributeMaxDynamicSharedMemorySize, gemm_smem);
    cudaFuncSetAttribute(scores_mma, cudaFuncAttributeMaxDynamicSharedMemorySize, scores_smem);
    cudaFuncSetAttribute(attn_mma, cudaFuncAttributeMaxDynamicSharedMemorySize, attn_smem);

    detect_mask_kind<<<1, 256>>>(mask);

    const size_t inN = (size_t)M_ * D_;
    const size_t wN  = (size_t)D_ * D_;
    cvt_hilo<<<(int)(inN / 4 / 256), 256>>>(Q, inh + 0 * inN, inl + 0 * inN, (int)(inN / 4));
    cvt_hilo<<<(int)(inN / 4 / 256), 256>>>(K, inh + 1 * inN, inl + 1 * inN, (int)(inN / 4));
    cvt_hilo<<<(int)(inN / 4 / 256), 256>>>(V, inh + 2 * inN, inl + 2 * inN, (int)(inN / 4));
    Src4 s4; s4.p[0] = Wq; s4.p[1] = Wk; s4.p[2] = Wv; s4.p[3] = Wo;
    cvt_hilo4<<<dim3((int)(wN / 4 / 256), 1, 4), 256>>>(s4, wth, wtl, (int)(wN / 4));

    Bias3 bqkv; bqkv.p[0] = bq; bqkv.p[1] = bk; bqkv.p[2] = bv;
    gemm_mma<1><<<dim3(D_ / 128, M_ / 128, 3), 256, gemm_smem>>>(
        inh, inl, wth, wtl, bqkv, nullptr, pjh, pjl);

    scores_mma<<<dim3(N_ / 128, N_ / 128, BH_), 256, scores_smem>>>(mask, wout);
    softmax_rows<<<BH_ * N_, 256>>>(wout);
    attn_mma<<<dim3(N_ / 128, BH_), 256, attn_smem>>>();

    Bias3 bout; bout.p[0] = bo; bout.p[1] = bo; bout.p[2] = bo;
    gemm_mma<0><<<dim3(D_ / 128, M_ / 128, 1), 256, gemm_smem>>>(
        ah, al, wth + 3 * wN, wtl + 3 * wN, bout, xout, nullptr, nullptr);
}

// round 13
// speedup vs baseline: 1.1724x; 1.0070x over previous
#include <cuda_runtime.h>
#include <cuda_bf16.h>
#include <cstdint>

// Problem constants
#define B_   4
#define N_   1024
#define D_   1024
#define H_   16
#define DH_  64
#define M_   (B_ * N_)    // 4096
#define BH_  (B_ * H_)    // 64

// Scratch (allocation-free rule: __device__ globals)
__device__ __nv_bfloat16 g_pjh[3][(size_t)M_ * D_];   // projected q,k,v hi
__device__ __nv_bfloat16 g_pjl[3][(size_t)M_ * D_];   // projected q,k,v lo
__device__ __nv_bfloat16 g_inh[3][(size_t)M_ * D_];
__device__ __nv_bfloat16 g_inl[3][(size_t)M_ * D_];
__device__ __nv_bfloat16 g_wth[4][(size_t)D_ * D_];
__device__ __nv_bfloat16 g_wtl[4][(size_t)D_ * D_];
__device__ __nv_bfloat16 g_wh[(size_t)BH_ * N_ * N_]; // softmaxed weights hi
__device__ __nv_bfloat16 g_wl[(size_t)BH_ * N_ * N_]; // softmaxed weights lo
__device__ __nv_bfloat16 g_ah[(size_t)M_ * D_];
__device__ __nv_bfloat16 g_al[(size_t)M_ * D_];
__device__ int   g_mask4;

struct Bias3 { const float* p[3]; };
struct Src4  { const float* p[4]; };

// ===========================================================================
// Helpers (generic PTX, sm_80+ only)
// ===========================================================================
__device__ __forceinline__ uint32_t smem_u32(const void* p) {
    uint32_t a;
    asm("{ .reg .u64 t; cvta.to.shared.u64 t, %1; cvt.u32.u64 %0, t; }" : "=r"(a) : "l"(p));
    return a;
}
__device__ __forceinline__ void ldsm_x4(uint32_t* r, uint32_t addr) {
    asm volatile("ldmatrix.sync.aligned.m8n8.x4.shared.b16 {%0,%1,%2,%3}, [%4];"
                 : "=r"(r[0]), "=r"(r[1]), "=r"(r[2]), "=r"(r[3]) : "r"(addr));
}
__device__ __forceinline__ void ldsm_x4_t(uint32_t* r, uint32_t addr) {
    asm volatile("ldmatrix.sync.aligned.m8n8.x4.trans.shared.b16 {%0,%1,%2,%3}, [%4];"
                 : "=r"(r[0]), "=r"(r[1]), "=r"(r[2]), "=r"(r[3]) : "r"(addr));
}
__device__ __forceinline__ void mma_bf16(float* c, const uint32_t* a, const uint32_t* b) {
    asm volatile(
        "mma.sync.aligned.m16n8k16.row.col.f32.bf16.bf16.f32 "
        "{%0,%1,%2,%3}, {%4,%5,%6,%7}, {%8,%9}, {%0,%1,%2,%3};"
        : "+f"(c[0]), "+f"(c[1]), "+f"(c[2]), "+f"(c[3])
        : "r"(a[0]), "r"(a[1]), "r"(a[2]), "r"(a[3]), "r"(b[0]), "r"(b[1]));
}
__device__ __forceinline__ void cp16(uint32_t smem, const void* g) {
    asm volatile("cp.async.ca.shared.global [%0], [%1], 16;" :: "r"(smem), "l"(g));
}
__device__ __forceinline__ void cp_commit() { asm volatile("cp.async.commit_group;"); }
template <int N>
__device__ __forceinline__ void cp_wait() { asm volatile("cp.async.wait_group %0;" :: "n"(N)); }

// ===========================================================================
// fp32 -> bf16 hi/lo conversion
// ===========================================================================
__device__ __forceinline__ void cvt_body(const float* __restrict__ src,
                                         __nv_bfloat16* __restrict__ dh,
                                         __nv_bfloat16* __restrict__ dl, int i) {
    float4 v = ((const float4*)src)[i];
    __nv_bfloat16 h0 = __float2bfloat16(v.x), h1 = __float2bfloat16(v.y);
    __nv_bfloat16 h2 = __float2bfloat16(v.z), h3 = __float2bfloat16(v.w);
    __nv_bfloat16 l0 = __float2bfloat16(v.x - __bfloat162float(h0));
    __nv_bfloat16 l1 = __float2bfloat16(v.y - __bfloat162float(h1));
    __nv_bfloat16 l2 = __float2bfloat16(v.z - __bfloat162float(h2));
    __nv_bfloat16 l3 = __float2bfloat16(v.w - __bfloat162float(h3));
    ((__nv_bfloat162*)dh)[i * 2]     = __nv_bfloat162(h0, h1);
    ((__nv_bfloat162*)dh)[i * 2 + 1] = __nv_bfloat162(h2, h3);
    ((__nv_bfloat162*)dl)[i * 2]     = __nv_bfloat162(l0, l1);
    ((__nv_bfloat162*)dl)[i * 2 + 1] = __nv_bfloat162(l2, l3);
}
__global__ void cvt_hilo(const float* __restrict__ src,
                         __nv_bfloat16* __restrict__ dh,
                         __nv_bfloat16* __restrict__ dl, int n4) {
    const int i = blockIdx.x * blockDim.x + threadIdx.x;
    if (i < n4) cvt_body(src, dh, dl, i);
}
__global__ void cvt_hilo4(Src4 s4, __nv_bfloat16* __restrict__ dh,
                          __nv_bfloat16* __restrict__ dl, int n4) {
    const int i = blockIdx.x * blockDim.x + threadIdx.x;
    const int z = blockIdx.z;
    if (i < n4) cvt_body(s4.p[z], dh + (size_t)z * D_ * D_, dl + (size_t)z * D_ * D_, i);
}

// ===========================================================================
// bf16x3 NT GEMM (R6 2-stage, z-batched), occupancy 2. (unchanged from R12)
// ===========================================================================
#define BK_      32
#define LDS_     40
#define TILE_B   (128 * LDS_ * 2)
#define BUF_B    (4 * TILE_B)
#define NUM_KB   (D_ / BK_)

template <int MODE>
__global__ void __launch_bounds__(256, 2) gemm_mma(const __nv_bfloat16* __restrict__ Ah,
                                                   const __nv_bfloat16* __restrict__ Al,
                                                   const __nv_bfloat16* __restrict__ Bh,
                                                   const __nv_bfloat16* __restrict__ Bl,
                                                   Bias3 b3,
                                                   float* __restrict__ C,
                                                   __nv_bfloat16* __restrict__ Chi,
                                                   __nv_bfloat16* __restrict__ Clo) {
    extern __shared__ char smem[];
    __shared__ float s_bias[128];

    const int z = blockIdx.z;
    Ah += (size_t)z * M_ * D_;
    Al += (size_t)z * M_ * D_;
    Bh += (size_t)z * D_ * D_;
    Bl += (size_t)z * D_ * D_;
    const float* bias = b3.p[z];
    if (MODE == 1) { Chi += (size_t)z * M_ * D_; Clo += (size_t)z * M_ * D_; }

    const int tid = threadIdx.x;
    const int wid = tid >> 5;
    const int lane = tid & 31;
    const int warp_m = wid >> 2;
    const int warp_n = wid & 3;
    const int row0 = blockIdx.y * 128;
    const int col0 = blockIdx.x * 128;

    if (tid < 128) s_bias[tid] = bias[col0 + tid];

    const int r  = tid >> 1;
    const int half = tid & 1;
    const __nv_bfloat16* Ah_p = Ah + (size_t)(row0 + r) * D_ + half * 16;
    const __nv_bfloat16* Al_p = Al + (size_t)(row0 + r) * D_ + half * 16;
    const __nv_bfloat16* Bh_p = Bh + (size_t)(col0 + r) * D_ + half * 16;
    const __nv_bfloat16* Bl_p = Bl + (size_t)(col0 + r) * D_ + half * 16;
    const uint32_t sb = smem_u32(smem);
    const uint32_t st = sb + (uint32_t)r * (LDS_ * 2) + (uint32_t)half * 32;

    const int seg = lane >> 3, l7 = lane & 7;
    const int a_row = warp_m * 64 + (seg & 1) * 8 + l7;
    const int a_colb = (((seg >> 1) & 1) * 8) * 2;
    const int b_row = warp_n * 32 + ((seg >> 1) & 1) * 8 + l7;
    const int b_colb = ((seg & 1) * 8) * 2;

    float acc[4][4][4] = {};

    {
        cp16(st + 0*TILE_B,      Ah_p);
        cp16(st + 0*TILE_B + 16, Ah_p + 8);
        cp16(st + 1*TILE_B,      Al_p);
        cp16(st + 1*TILE_B + 16, Al_p + 8);
        cp16(st + 2*TILE_B,      Bh_p);
        cp16(st + 2*TILE_B + 16, Bh_p + 8);
        cp16(st + 3*TILE_B,      Bl_p);
        cp16(st + 3*TILE_B + 16, Bl_p + 8);
        cp_commit();
    }

    for (int kb = 0; kb < NUM_KB; kb++) {
        if (kb + 1 < NUM_KB) {
            const int k0 = (kb + 1) * BK_;
            const uint32_t nst = st + (uint32_t)((kb + 1) & 1) * BUF_B;
            cp16(nst + 0*TILE_B,      Ah_p + k0);
            cp16(nst + 0*TILE_B + 16, Ah_p + k0 + 8);
            cp16(nst + 1*TILE_B,      Al_p + k0);
            cp16(nst + 1*TILE_B + 16, Al_p + k0 + 8);
            cp16(nst + 2*TILE_B,      Bh_p + k0);
            cp16(nst + 2*TILE_B + 16, Bh_p + k0 + 8);
            cp16(nst + 3*TILE_B,      Bl_p + k0);
            cp16(nst + 3*TILE_B + 16, Bl_p + k0 + 8);
            cp_commit();
            cp_wait<1>();
        } else {
            cp_wait<0>();
        }
        __syncthreads();

        const uint32_t buf = sb + (uint32_t)(kb & 1) * BUF_B;
#pragma unroll
        for (int s = 0; s < 2; s++) {
            uint32_t a_hi[4][4], a_lo[4][4], b_hi[4][2], b_lo[4][2];
#pragma unroll
            for (int mt = 0; mt < 4; mt++) {
                const uint32_t off = (uint32_t)(a_row + mt * 16) * (LDS_ * 2) + a_colb + s * 32;
                ldsm_x4(a_hi[mt], buf + 0 * TILE_B + off);
                ldsm_x4(a_lo[mt], buf + 1 * TILE_B + off);
            }
#pragma unroll
            for (int p = 0; p < 2; p++) {
                const uint32_t off = (uint32_t)(b_row + p * 16) * (LDS_ * 2) + b_colb + s * 32;
                uint32_t th[4], tl[4];
                ldsm_x4(th, buf + 2 * TILE_B + off);
                ldsm_x4(tl, buf + 3 * TILE_B + off);
                b_hi[2*p][0] = th[0]; b_hi[2*p][1] = th[1];
                b_hi[2*p+1][0] = th[2]; b_hi[2*p+1][1] = th[3];
                b_lo[2*p][0] = tl[0]; b_lo[2*p][1] = tl[1];
                b_lo[2*p+1][0] = tl[2]; b_lo[2*p+1][1] = tl[3];
            }
#pragma unroll
            for (int mt = 0; mt < 4; mt++)
#pragma unroll
                for (int nt = 0; nt < 4; nt++) {
                    mma_bf16(acc[mt][nt], a_hi[mt], b_hi[nt]);
                    mma_bf16(acc[mt][nt], a_lo[mt], b_hi[nt]);
                    mma_bf16(acc[mt][nt], a_hi[mt], b_lo[nt]);
                }
        }
        __syncthreads();
    }

    const int group = lane >> 2, tg = lane & 3;
#pragma unroll
    for (int mt = 0; mt < 4; mt++) {
#pragma unroll
        for (int nt = 0; nt < 4; nt++) {
#pragma unroll
            for (int rp = 0; rp < 2; rp++) {
                const int row = row0 + warp_m * 64 + mt * 16 + group + rp * 8;
                const int lcol = warp_n * 32 + nt * 8 + tg * 2;
                const float v0 = acc[mt][nt][rp * 2 + 0] + s_bias[lcol];
                const float v1 = acc[mt][nt][rp * 2 + 1] + s_bias[lcol + 1];
                if (MODE == 0) {
                    C[(size_t)row * D_ + col0 + lcol] = v0;
                    C[(size_t)row * D_ + col0 + lcol + 1] = v1;
                } else {
                    const int b = row >> 10;
                    const int n = row & (N_ - 1);
                    const int col = col0 + lcol;
                    const int h = col >> 6;
                    const int dh = col & (DH_ - 1);
                    const size_t idx = (((size_t)b * H_ + h) * N_ + n) * DH_ + dh;
                    __nv_bfloat16 h0 = __float2bfloat16(v0);
                    __nv_bfloat16 h1 = __float2bfloat16(v1);
                    __nv_bfloat16 l0 = __float2bfloat16(v0 - __bfloat162float(h0));
                    __nv_bfloat16 l1 = __float2bfloat16(v1 - __bfloat162float(h1));
                    *(__nv_bfloat162*)(Chi + idx) = __nv_bfloat162(h0, h1);
                    *(__nv_bfloat162*)(Clo + idx) = __nv_bfloat162(l0, l1);
                }
            }
        }
    }
}

// ===========================================================================
// Mask dtype detection (unchanged)
// ===========================================================================
__global__ void detect_mask_kind(const unsigned char* __restrict__ m) {
    __shared__ int has_gt1, has_mis;
    if (threadIdx.x == 0) { has_gt1 = 0; has_mis = 0; }
    __syncthreads();
    int lg = 0, lm = 0;
    for (int i = threadIdx.x * 16; i < 65536; i += blockDim.x * 16) {
        uint4 v = *(const uint4*)(m + i);
        unsigned int w[4] = {v.x, v.y, v.z, v.w};
#pragma unroll
        for (int j = 0; j < 4; j++) {
#pragma unroll
            for (int b = 0; b < 4; b++) {
                unsigned int byte = (w[j] >> (8 * b)) & 0xFFu;
                int pos = i + j * 4 + b;
                if (byte > 1u) lg = 1;
                if (byte != 0u && (pos & 3)) lm = 1;
            }
        }
    }
    if (lg) atomicOr(&has_gt1, 1);
    if (lm) atomicOr(&has_mis, 1);
    __syncthreads();
    if (threadIdx.x == 0) g_mask4 = (has_gt1 || !has_mis) ? 1 : 0;
}

// ===========================================================================
// Scores via mma, bf16x3, occ 2. (unchanged from R12)
// ===========================================================================
#define LDQ  72
#define QT_B (128 * LDQ * 2)

__global__ void __launch_bounds__(256, 2) scores_mma(const unsigned char* __restrict__ maskp,
                                                     float* __restrict__ wout) {
    extern __shared__ char smem[];
    const int tid = threadIdx.x;
    const int wid = tid >> 5;
    const int lane = tid & 31;
    const int warp_m = wid >> 2;
    const int warp_n = wid & 3;
    const int bh = blockIdx.z;
    const int row0 = blockIdx.y * 128;
    const int col0 = blockIdx.x * 128;

    const int r = tid >> 1;
    const int half = tid & 1;
    const size_t qsrc = (size_t)bh * N_ * DH_ + (size_t)(row0 + r) * DH_ + half * 32;
    const size_t ksrc = (size_t)bh * N_ * DH_ + (size_t)(col0 + r) * DH_ + half * 32;
    const uint32_t dst = (uint32_t)r * (LDQ * 2) + (uint32_t)half * 64;
#pragma unroll
    for (int j = 0; j < 4; j++) {
        *(uint4*)(smem + 0*QT_B + dst + j*16) = *(const uint4*)(g_pjh[0] + qsrc + j*8);
        *(uint4*)(smem + 1*QT_B + dst + j*16) = *(const uint4*)(g_pjl[0] + qsrc + j*8);
        *(uint4*)(smem + 2*QT_B + dst + j*16) = *(const uint4*)(g_pjh[1] + ksrc + j*8);
        *(uint4*)(smem + 3*QT_B + dst + j*16) = *(const uint4*)(g_pjl[1] + ksrc + j*8);
    }
    __syncthreads();

    const uint32_t sb = smem_u32(smem);
    const int seg = lane >> 3, l7 = lane & 7;
    const int a_row = warp_m * 64 + (seg & 1) * 8 + l7;
    const int a_colb = (((seg >> 1) & 1) * 8) * 2;
    const int b_row = warp_n * 32 + ((seg >> 1) & 1) * 8 + l7;
    const int b_colb = ((seg & 1) * 8) * 2;

    float acc[4][4][4] = {};
#pragma unroll
    for (int s = 0; s < 4; s++) {
        uint32_t a_hi[4][4], a_lo[4][4], b_hi[4][2], b_lo[4][2];
#pragma unroll
        for (int mt = 0; mt < 4; mt++) {
            const uint32_t off = (uint32_t)(a_row + mt * 16) * (LDQ * 2) + a_colb + s * 32;
            ldsm_x4(a_hi[mt], sb + 0 * QT_B + off);
            ldsm_x4(a_lo[mt], sb + 1 * QT_B + off);
        }
#pragma unroll
        for (int p = 0; p < 2; p++) {
            const uint32_t off = (uint32_t)(b_row + p * 16) * (LDQ * 2) + b_colb + s * 32;
            uint32_t th[4], tl[4];
            ldsm_x4(th, sb + 2 * QT_B + off);
            ldsm_x4(tl, sb + 3 * QT_B + off);
            b_hi[2*p][0] = th[0]; b_hi[2*p][1] = th[1];
            b_hi[2*p+1][0] = th[2]; b_hi[2*p+1][1] = th[3];
            b_lo[2*p][0] = tl[0]; b_lo[2*p][1] = tl[1];
            b_lo[2*p+1][0] = tl[2]; b_lo[2*p+1][1] = tl[3];
        }
#pragma unroll
        for (int mt = 0; mt < 4; mt++)
#pragma unroll
            for (int nt = 0; nt < 4; nt++) {
                mma_bf16(acc[mt][nt], a_hi[mt], b_hi[nt]);
                mma_bf16(acc[mt][nt], a_lo[mt], b_hi[nt]);
                mma_bf16(acc[mt][nt], a_hi[mt], b_lo[nt]);
            }
    }

    const int group = lane >> 2, tg = lane & 3;
    const int m4 = g_mask4;
    const unsigned int* mask32 = (const unsigned int*)maskp;
#pragma unroll
    for (int mt = 0; mt < 4; mt++)
#pragma unroll
        for (int nt = 0; nt < 4; nt++)
#pragma unroll
            for (int rg = 0; rg < 4; rg++) {
                const int row = row0 + warp_m * 64 + mt * 16 + group + (rg >> 1) * 8;
                const int col = col0 + warp_n * 32 + nt * 8 + tg * 2 + (rg & 1);
                const size_t idx = ((size_t)bh * N_ + row) * N_ + col;
                const bool masked = m4 ? (mask32[idx] != 0u) : (maskp[idx] != 0);
                wout[idx] = masked ? -1e10f : acc[mt][nt][rg] * 0.125f;
            }
}

// ===========================================================================
// Row softmax, WARP-PER-ROW: 8 rows/block, pure shfl reductions, no barriers.
// Writes fp32 weights in place + bf16 hi/lo copies.
// ===========================================================================
__global__ void __launch_bounds__(256) softmax_rows(float* __restrict__ w) {
    const int warp = threadIdx.x >> 5, lane = threadIdx.x & 31;
    const size_t row = (size_t)blockIdx.x * 8 + warp;
    float* p = w + row * N_;

    float4 v[8];
#pragma unroll
    for (int j = 0; j < 8; j++) v[j] = ((const float4*)p)[lane + j * 32];

    float m = -3.4e38f;
#pragma unroll
    for (int j = 0; j < 8; j++)
        m = fmaxf(m, fmaxf(fmaxf(v[j].x, v[j].y), fmaxf(v[j].z, v[j].w)));
#pragma unroll
    for (int o = 16; o; o >>= 1) m = fmaxf(m, __shfl_xor_sync(~0u, m, o));

    float s = 0.0f;
#pragma unroll
    for (int j = 0; j < 8; j++) {
        v[j].x = __expf(v[j].x - m); v[j].y = __expf(v[j].y - m);
        v[j].z = __expf(v[j].z - m); v[j].w = __expf(v[j].w - m);
        s += v[j].x + v[j].y + v[j].z + v[j].w;
    }
#pragma unroll
    for (int o = 16; o; o >>= 1) s += __shfl_xor_sync(~0u, s, o);
    const float inv = 1.0f / s;

#pragma unroll
    for (int j = 0; j < 8; j++) {
        v[j].x *= inv; v[j].y *= inv; v[j].z *= inv; v[j].w *= inv;
        ((float4*)p)[lane + j * 32] = v[j];
        __nv_bfloat16 h0 = __float2bfloat16(v[j].x), h1 = __float2bfloat16(v[j].y);
        __nv_bfloat16 h2 = __float2bfloat16(v[j].z), h3 = __float2bfloat16(v[j].w);
        __nv_bfloat16 l0 = __float2bfloat16(v[j].x - __bfloat162float(h0));
        __nv_bfloat16 l1 = __float2bfloat16(v[j].y - __bfloat162float(h1));
        __nv_bfloat16 l2 = __float2bfloat16(v[j].z - __bfloat162float(h2));
        __nv_bfloat16 l3 = __float2bfloat16(v[j].w - __bfloat162float(h3));
        const size_t off = row * N_ + (size_t)(lane + j * 32) * 4;
        *(__nv_bfloat162*)(g_wh + off)     = __nv_bfloat162(h0, h1);
        *(__nv_bfloat162*)(g_wh + off + 2) = __nv_bfloat162(h2, h3);
        *(__nv_bfloat162*)(g_wl + off)     = __nv_bfloat162(l0, l1);
        *(__nv_bfloat162*)(g_wl + off + 2) = __nv_bfloat162(l2, l3);
    }
}

// ===========================================================================
// attn = weights @ v via mma, bf16x3, occ 2, cp.async double-buffered staging.
// ===========================================================================
#define AT_B   (128 * LDQ * 2)
#define VT_B   (64 * LDQ * 2)
#define AB_B   (2 * AT_B + 2 * VT_B)
#define NKB_A  (N_ / 64)

__global__ void __launch_bounds__(256, 2) attn_mma(void) {
    extern __shared__ char smem[];
    const int tid = threadIdx.x;
    const int wid = tid >> 5;
    const int lane = tid & 31;
    const int warp_m = wid >> 1;
    const int warp_n = wid & 1;
    const int bh = blockIdx.y;
    const int row0 = blockIdx.x * 128;

    const __nv_bfloat16* whb = g_wh + (size_t)bh * N_ * N_;
    const __nv_bfloat16* wlb = g_wl + (size_t)bh * N_ * N_;
    const __nv_bfloat16* vhb = g_pjh[2] + (size_t)bh * N_ * DH_;
    const __nv_bfloat16* vlb = g_pjl[2] + (size_t)bh * N_ * DH_;

    const uint32_t sb = smem_u32(smem);
    const int ar = tid >> 1, ahalf = tid & 1;
    const uint32_t a_dst = sb + (uint32_t)ar * (LDQ * 2) + (uint32_t)ahalf * 64;
    const int vr = tid >> 2, vq = tid & 3;
    const uint32_t v_dst = sb + (uint32_t)vr * (LDQ * 2) + (uint32_t)vq * 32;

    const __nv_bfloat16* wh_p = whb + (size_t)(row0 + ar) * N_ + ahalf * 32;
    const __nv_bfloat16* wl_p = wlb + (size_t)(row0 + ar) * N_ + ahalf * 32;
    const __nv_bfloat16* vh_p = vhb + (size_t)vr * DH_ + vq * 16;
    const __nv_bfloat16* vl_p = vlb + (size_t)vr * DH_ + vq * 16;

    // prologue: stage chunk 0 into buffer 0
    {
        cp16(a_dst + 0*AT_B,      wh_p);
        cp16(a_dst + 0*AT_B + 16, wh_p + 8);
        cp16(a_dst + 0*AT_B + 32, wh_p + 16);
        cp16(a_dst + 0*AT_B + 48, wh_p + 24);
        cp16(a_dst + 1*AT_B,      wl_p);
        cp16(a_dst + 1*AT_B + 16, wl_p + 8);
        cp16(a_dst + 1*AT_B + 32, wl_p + 16);
        cp16(a_dst + 1*AT_B + 48, wl_p + 24);
        cp16(v_dst + 2*AT_B + 0*VT_B,      vh_p);
        cp16(v_dst + 2*AT_B + 0*VT_B + 16, vh_p + 8);
        cp16(v_dst + 2*AT_B + 1*VT_B,      vl_p);
        cp16(v_dst + 2*AT_B + 1*VT_B + 16, vl_p + 8);
        cp_commit();
    }

    const int l15 = lane & 15;
    const int a_row = warp_m * 32 + l15;
    const int a_colb = (lane >> 4) * 16;
    const int v_row = l15;
    const int v_colb = (warp_n * 32) * 2 + (lane >> 4) * 16;

    float acc[2][4][4] = {};

    for (int kb = 0; kb < NKB_A; kb++) {
        if (kb + 1 < NKB_A) {
            const int k0 = (kb + 1) * 64;
            const uint32_t boff = (uint32_t)((kb + 1) & 1) * AB_B;
            const size_t vk = (size_t)k0 * DH_;
            cp16(boff + a_dst + 0*AT_B,      wh_p + k0);
            cp16(boff + a_dst + 0*AT_B + 16, wh_p + k0 + 8);
            cp16(boff + a_dst + 0*AT_B + 32, wh_p + k0 + 16);
            cp16(boff + a_dst + 0*AT_B + 48, wh_p + k0 + 24);
            cp16(boff + a_dst + 1*AT_B,      wl_p + k0);
            cp16(boff + a_dst + 1*AT_B + 16, wl_p + k0 + 8);
            cp16(boff + a_dst + 1*AT_B + 32, wl_p + k0 + 16);
            cp16(boff + a_dst + 1*AT_B + 48, wl_p + k0 + 24);
            cp16(boff + v_dst + 2*AT_B + 0*VT_B,      vh_p + vk);
            cp16(boff + v_dst + 2*AT_B + 0*VT_B + 16, vh_p + vk + 8);
            cp16(boff + v_dst + 2*AT_B + 1*VT_B,      vl_p + vk);
            cp16(boff + v_dst + 2*AT_B + 1*VT_B + 16, vl_p + vk + 8);
            cp_commit();
            cp_wait<1>();
        } else {
            cp_wait<0>();
        }
        __syncthreads();

        const uint32_t buf = sb + (uint32_t)(kb & 1) * AB_B;
#pragma unroll
        for (int s = 0; s < 4; s++) {
            uint32_t a_hi[2][4], a_lo[2][4], b_hi[4][2], b_lo[4][2];
#pragma unroll
            for (int mt = 0; mt < 2; mt++) {
                const uint32_t off = (uint32_t)(a_row + mt * 16) * (LDQ * 2) + a_colb + s * 32;
                ldsm_x4(a_hi[mt], buf + 0 * AT_B + off);
                ldsm_x4(a_lo[mt], buf + 1 * AT_B + off);
            }
#pragma unroll
            for (int p = 0; p < 2; p++) {
                const uint32_t off = (uint32_t)(s * 16 + v_row) * (LDQ * 2) + v_colb + p * 32;
                uint32_t th[4], tl[4];
                ldsm_x4_t(th, buf + 2 * AT_B + 0 * VT_B + off);
                ldsm_x4_t(tl, buf + 2 * AT_B + 1 * VT_B + off);
                b_hi[2*p][0] = th[0]; b_hi[2*p][1] = th[1];
                b_hi[2*p+1][0] = th[2]; b_hi[2*p+1][1] = th[3];
                b_lo[2*p][0] = tl[0]; b_lo[2*p][1] = tl[1];
                b_lo[2*p+1][0] = tl[2]; b_lo[2*p+1][1] = tl[3];
            }
#pragma unroll
            for (int mt = 0; mt < 2; mt++)
#pragma unroll
                for (int nt = 0; nt < 4; nt++) {
                    mma_bf16(acc[mt][nt], a_hi[mt], b_hi[nt]);
                    mma_bf16(acc[mt][nt], a_lo[mt], b_hi[nt]);
                    mma_bf16(acc[mt][nt], a_hi[mt], b_lo[nt]);
                }
        }
        __syncthreads();
    }

    const int b = bh >> 4;
    const int h = bh & (H_ - 1);
    const int group = lane >> 2, tg = lane & 3;
#pragma unroll
    for (int mt = 0; mt < 2; mt++)
#pragma unroll
        for (int nt = 0; nt < 4; nt++)
#pragma unroll
            for (int rp = 0; rp < 2; rp++) {
                const int n = row0 + warp_m * 32 + mt * 16 + group + rp * 8;
                const int dh = warp_n * 32 + nt * 8 + tg * 2;
                const float v0 = acc[mt][nt][rp * 2 + 0];
                const float v1 = acc[mt][nt][rp * 2 + 1];
                const size_t idx = ((size_t)b * N_ + n) * D_ + h * DH_ + dh;
                __nv_bfloat16 h0 = __float2bfloat16(v0);
                __nv_bfloat16 h1 = __float2bfloat16(v1);
                __nv_bfloat16 l0 = __float2bfloat16(v0 - __bfloat162float(h0));
                __nv_bfloat16 l1 = __float2bfloat16(v1 - __bfloat162float(h1));
                *(__nv_bfloat162*)(g_ah + idx) = __nv_bfloat162(h0, h1);
                *(__nv_bfloat162*)(g_al + idx) = __nv_bfloat162(l0, l1);
            }
}

// ===========================================================================
extern "C" void kernel_launch(void* const* d_in, const int* in_sizes, int n_in,
                              void* d_out, int out_size) {
    const float* Q  = (const float*)d_in[0];
    const float* K  = (const float*)d_in[1];
    const float* V  = (const float*)d_in[2];
    const unsigned char* mask = (const unsigned char*)d_in[3];
    const float* Wq = (const float*)d_in[4];
    const float* bq = (const float*)d_in[5];
    const float* Wk = (const float*)d_in[6];
    const float* bk = (const float*)d_in[7];
    const float* Wv = (const float*)d_in[8];
    const float* bv = (const float*)d_in[9];
    const float* Wo = (const float*)d_in[10];
    const float* bo = (const float*)d_in[11];

    float* xout = (float*)d_out;
    float* wout = xout + (size_t)M_ * D_;

    __nv_bfloat16 *pjh, *pjl, *inh, *inl, *wth, *wtl, *ah, *al;
    cudaGetSymbolAddress((void**)&pjh, g_pjh);
    cudaGetSymbolAddress((void**)&pjl, g_pjl);
    cudaGetSymbolAddress((void**)&inh, g_inh);
    cudaGetSymbolAddress((void**)&inl, g_inl);
    cudaGetSymbolAddress((void**)&wth, g_wth);
    cudaGetSymbolAddress((void**)&wtl, g_wtl);
    cudaGetSymbolAddress((void**)&ah, g_ah);
    cudaGetSymbolAddress((void**)&al, g_al);

    const int gemm_smem = 2 * BUF_B;       // 81920
    const int scores_smem = 4 * QT_B;      // 73728
    const int attn_smem = 2 * AB_B;        // 110592
    cudaFuncSetAttribute(gemm_mma<0>, cudaFuncAttributeMaxDynamicSharedMemorySize, gemm_smem);
    cudaFuncSetAttribute(gemm_mma<1>, cudaFuncAttributeMaxDynamicSharedMemorySize, gemm_smem);
    cudaFuncSetAttribute(scores_mma, cudaFuncAttributeMaxDynamicSharedMemorySize, scores_smem);
    cudaFuncSetAttribute(attn_mma, cudaFuncAttributeMaxDynamicSharedMemorySize, attn_smem);

    detect_mask_kind<<<1, 256>>>(mask);

    const size_t inN = (size_t)M_ * D_;
    const size_t wN  = (size_t)D_ * D_;
    cvt_hilo<<<(int)(inN / 4 / 256), 256>>>(Q, inh + 0 * inN, inl + 0 * inN, (int)(inN / 4));
    cvt_hilo<<<(int)(inN / 4 / 256), 256>>>(K, inh + 1 * inN, inl + 1 * inN, (int)(inN / 4));
    cvt_hilo<<<(int)(inN / 4 / 256), 256>>>(V, inh + 2 * inN, inl + 2 * inN, (int)(inN / 4));
    Src4 s4; s4.p[0] = Wq; s4.p[1] = Wk; s4.p[2] = Wv; s4.p[3] = Wo;
    cvt_hilo4<<<dim3((int)(wN / 4 / 256), 1, 4), 256>>>(s4, wth, wtl, (int)(wN / 4));

    Bias3 bqkv; bqkv.p[0] = bq; bqkv.p[1] = bk; bqkv.p[2] = bv;
    gemm_mma<1><<<dim3(D_ / 128, M_ / 128, 3), 256, gemm_smem>>>(
        inh, inl, wth, wtl, bqkv, nullptr, pjh, pjl);

    scores_mma<<<dim3(N_ / 128, N_ / 128, BH_), 256, scores_smem>>>(mask, wout);
    softmax_rows<<<BH_ * N_ / 8, 256>>>(wout);
    attn_mma<<<dim3(N_ / 128, BH_), 256, attn_smem>>>();

    Bias3 bout; bout.p[0] = bo; bout.p[1] = bo; bout.p[2] = bo;
    gemm_mma<0><<<dim3(D_ / 128, M_ / 128, 1), 256, gemm_smem>>>(
        ah, al, wth + 3 * wN, wtl + 3 * wN, bout, xout, nullptr, nullptr);
}